// round 3
// baseline (speedup 1.0000x reference)
#include <cuda_runtime.h>
#include <math.h>

#define NB   8
#define CIN  96
#define COUT 192
#define C2   48
#define NCH  (NB*C2)     // 384 channels of 256x256

// Static scratch (allowed; no runtime allocation)
__device__ float2 g_tab[256];
__device__ float  y_buf[NCH*256*256];   // pixel-shuffled conv output, ~100MB
__device__ float2 t_buf[NCH*256*256];   // row-transformed (complex), ~201MB

// ---------------------------------------------------------------------------
// g[d] = (1/256) * sum_{k=-64}^{63} e^{2*pi*i*k*d/256}
//   d==0: 0.5 ; even d: 0 ; odd d: (2/256)*e^{-i*pi*d/2}/(1 - e^{i*pi*d/128})
// ---------------------------------------------------------------------------
__global__ void init_g_kernel() {
    int d = threadIdx.x;
    float2 g;
    if (d == 0) { g.x = 0.5f; g.y = 0.0f; }
    else if ((d & 1) == 0) { g.x = 0.0f; g.y = 0.0f; }
    else {
        double nre, nim;                 // e^{-i*pi*d/2}, d odd
        if ((d & 3) == 1) { nre = 0.0; nim = -1.0; }
        else             { nre = 0.0; nim =  1.0; }
        double th  = 3.14159265358979323846 * (double)d / 128.0;
        double dre = 1.0 - cos(th);
        double dim = -sin(th);
        double den = dre*dre + dim*dim;
        double re = (nre*dre + nim*dim) / den;
        double im = (nim*dre - nre*dim) / den;
        g.x = (float)(re * 0.0078125);   // * 2/256
        g.y = (float)(im * 0.0078125);
    }
    g_tab[d] = g;
}

// ---------------------------------------------------------------------------
// Conv 3x3 (pad 1) fused with pixel-shuffle write.
// Block: 256 threads; covers 1 batch, 32 output channels, 16x16 spatial tile.
// Thread: 8 co x (2x2 pixel quad) = 32 fp32 accumulators.
// ---------------------------------------------------------------------------
__global__ __launch_bounds__(256, 4) void conv_ps_kernel(
    const float* __restrict__ x, const float* __restrict__ w)
{
    __shared__ float sx[8][18][20];      // 8 ci x 18x18 halo tile (padded)
    __shared__ float sw_[32][8][9];      // 32 co x 8 ci x 9 taps

    int t    = threadIdx.x;
    int tile = blockIdx.x;               // 0..63 (8x8 tiles of 16x16)
    int by   = (tile >> 3) * 16;
    int bx   = (tile & 7) * 16;
    int cob  = blockIdx.y * 32;
    int b    = blockIdx.z;
    int q    = t & 63;                   // quad id within 8x8
    int cog  = t >> 6;                   // 0..3 (co subgroup)
    int qy   = (q >> 3) * 2;
    int qx   = (q & 7) * 2;

    float acc[8][4];
    #pragma unroll
    for (int u = 0; u < 8; u++)
        #pragma unroll
        for (int p = 0; p < 4; p++) acc[u][p] = 0.f;

    for (int ci0 = 0; ci0 < CIN; ci0 += 8) {
        __syncthreads();
        for (int idx = t; idx < 8*18*18; idx += 256) {
            int ci  = idx / 324, rem = idx % 324;
            int iy  = rem / 18,  ix  = rem % 18;
            int gy  = by + iy - 1, gx = bx + ix - 1;
            float v = 0.f;
            if (gy >= 0 && gy < 128 && gx >= 0 && gx < 128)
                v = x[((b*CIN + ci0 + ci) * 128 + gy) * 128 + gx];
            sx[ci][iy][ix] = v;
        }
        for (int idx = t; idx < 32*8*9; idx += 256) {
            int co = idx / 72, rem = idx % 72;
            int ci = rem / 9,  tap = rem % 9;
            sw_[co][ci][tap] = w[((cob + co) * CIN + ci0 + ci) * 9 + tap];
        }
        __syncthreads();

        #pragma unroll 2
        for (int ci = 0; ci < 8; ci++) {
            #pragma unroll
            for (int tap = 0; tap < 9; tap++) {
                int ky = tap / 3, kx = tap % 3;
                float x00 = sx[ci][qy + ky    ][qx + kx    ];
                float x01 = sx[ci][qy + ky    ][qx + kx + 1];
                float x10 = sx[ci][qy + ky + 1][qx + kx    ];
                float x11 = sx[ci][qy + ky + 1][qx + kx + 1];
                #pragma unroll
                for (int u = 0; u < 8; u++) {
                    float wv = sw_[cog*8 + u][ci][tap];
                    acc[u][0] += wv * x00;
                    acc[u][1] += wv * x01;
                    acc[u][2] += wv * x10;
                    acc[u][3] += wv * x11;
                }
            }
        }
    }

    // pixel shuffle: y[b, co>>2, 2h+i, 2w+j] = y4[b, co, h, w], i=(co>>1)&1, j=co&1
    #pragma unroll
    for (int u = 0; u < 8; u++) {
        int co = cob + cog*8 + u;
        int c  = co >> 2;
        int i  = (co >> 1) & 1;
        int j  = co & 1;
        #pragma unroll
        for (int p = 0; p < 4; p++) {
            int py = by + qy + (p >> 1);
            int px = bx + qx + (p & 1);
            y_buf[((b*C2 + c) * 256 + (2*py + i)) * 256 + (2*px + j)] = acc[u][p];
        }
    }
}

// ---------------------------------------------------------------------------
// Rows transform: T[n][m2] = 0.5*Y[n][m2] + sum_{m opp parity} g[(n-m)&255]*Y[m][m2]
// Parity-split GEMM, K=128. Block: 64x64 output tile (rows same parity).
// ---------------------------------------------------------------------------
__global__ __launch_bounds__(256, 4) void gemm_rows_kernel() {
    __shared__ float2 gs[256];
    __shared__ float  Ys[16][68];

    int t  = threadIdx.x;
    int tx = t & 15, ty = t >> 4;
    int cb = blockIdx.x;                 // m2 tile (4 of 64)
    int nt = blockIdx.y;                 // n tile: parity p, half tb
    int ch = blockIdx.z;
    int p  = nt & 1, tb = nt >> 1;
    int qpar = 1 - p;

    gs[t] = g_tab[t];
    const float* Y = y_buf + ch * 65536;

    int n_[4];
    #pragma unroll
    for (int v = 0; v < 4; v++) n_[v] = p + 2 * (64*tb + ty + 16*v);

    float2 acc[4][4];
    #pragma unroll
    for (int v = 0; v < 4; v++)
        #pragma unroll
        for (int u = 0; u < 4; u++) { acc[v][u].x = 0.f; acc[v][u].y = 0.f; }

    for (int kb = 0; kb < 8; kb++) {
        __syncthreads();
        for (int idx = t; idx < 16*64; idx += 256) {
            int kk = idx >> 6, c = idx & 63;
            int m  = qpar + 2 * (kb*16 + kk);
            Ys[kk][c] = Y[m*256 + 64*cb + c];
        }
        __syncthreads();
        #pragma unroll
        for (int kk = 0; kk < 16; kk++) {
            int m = qpar + 2 * (kb*16 + kk);
            float2 gv[4]; float yv[4];
            #pragma unroll
            for (int v = 0; v < 4; v++) gv[v] = gs[(n_[v] - m) & 255];
            #pragma unroll
            for (int u = 0; u < 4; u++) yv[u] = Ys[kk][tx + 16*u];
            #pragma unroll
            for (int v = 0; v < 4; v++)
                #pragma unroll
                for (int u = 0; u < 4; u++) {
                    acc[v][u].x += gv[v].x * yv[u];
                    acc[v][u].y += gv[v].y * yv[u];
                }
        }
    }

    #pragma unroll
    for (int v = 0; v < 4; v++)
        #pragma unroll
        for (int u = 0; u < 4; u++) {
            int n  = n_[v];
            int m2 = 64*cb + tx + 16*u;
            float yd = Y[n*256 + m2];
            float2 r;
            r.x = acc[v][u].x + 0.5f * yd;
            r.y = acc[v][u].y;
            t_buf[ch*65536 + n*256 + m2] = r;
        }
}

// ---------------------------------------------------------------------------
// Cols transform + epilogue:
// Z[n1][n2] = 0.5*T[n1][n2] + sum_{m2 opp parity} T[n1][m2]*g[(n2-m2)&255]
// out = beta*y + (1-2*beta)*|Z|
// ---------------------------------------------------------------------------
__global__ __launch_bounds__(256, 4) void gemm_cols_kernel(
    const float* __restrict__ beta_ptr, float* __restrict__ out)
{
    __shared__ float2 gs[256];
    __shared__ float2 Ts[16][66];

    int t  = threadIdx.x;
    int tx = t & 15, ty = t >> 4;
    int ct = blockIdx.x;                 // n2 tile: parity p, half tb
    int rb = blockIdx.y;                 // n1 tile (4 of 64)
    int ch = blockIdx.z;
    int p  = ct & 1, tb = ct >> 1;
    int qpar = 1 - p;

    gs[t] = g_tab[t];
    const float2* T = t_buf + ch * 65536;

    int n2_[4];
    #pragma unroll
    for (int u = 0; u < 4; u++) n2_[u] = p + 2 * (64*tb + tx + 16*u);
    int n1_[4];
    #pragma unroll
    for (int v = 0; v < 4; v++) n1_[v] = 64*rb + ty + 16*v;

    float2 acc[4][4];
    #pragma unroll
    for (int v = 0; v < 4; v++)
        #pragma unroll
        for (int u = 0; u < 4; u++) { acc[v][u].x = 0.f; acc[v][u].y = 0.f; }

    for (int kb = 0; kb < 8; kb++) {
        __syncthreads();
        for (int idx = t; idx < 16*64; idx += 256) {
            int kk = idx & 15, r = idx >> 4;
            int m2 = qpar + 2 * (kb*16 + kk);
            Ts[kk][r] = T[(64*rb + r)*256 + m2];
        }
        __syncthreads();
        #pragma unroll
        for (int kk = 0; kk < 16; kk++) {
            int m2 = qpar + 2 * (kb*16 + kk);
            float2 tv[4]; float2 gv[4];
            #pragma unroll
            for (int v = 0; v < 4; v++) tv[v] = Ts[kk][ty + 16*v];
            #pragma unroll
            for (int u = 0; u < 4; u++) gv[u] = gs[(n2_[u] - m2) & 255];
            #pragma unroll
            for (int v = 0; v < 4; v++)
                #pragma unroll
                for (int u = 0; u < 4; u++) {
                    acc[v][u].x += tv[v].x * gv[u].x - tv[v].y * gv[u].y;
                    acc[v][u].y += tv[v].x * gv[u].y + tv[v].y * gv[u].x;
                }
        }
    }

    float beta = *beta_ptr;
    float cl   = 1.f - 2.f * beta;
    #pragma unroll
    for (int v = 0; v < 4; v++)
        #pragma unroll
        for (int u = 0; u < 4; u++) {
            int n1 = n1_[v], n2 = n2_[u];
            float2 td = T[n1*256 + n2];
            float zr = acc[v][u].x + 0.5f * td.x;
            float zi = acc[v][u].y + 0.5f * td.y;
            float low = sqrtf(zr*zr + zi*zi);
            float yv  = y_buf[ch*65536 + n1*256 + n2];
            out[ch*65536 + n1*256 + n2] = beta * yv + cl * low;
        }
}

// ---------------------------------------------------------------------------
extern "C" void kernel_launch(void* const* d_in, const int* in_sizes, int n_in,
                              void* d_out, int out_size)
{
    const float* x    = (const float*)d_in[0];
    const float* w    = (const float*)d_in[1];
    const float* beta = (const float*)d_in[2];
    float* out        = (float*)d_out;

    init_g_kernel<<<1, 256>>>();
    conv_ps_kernel<<<dim3(64, 6, NB), 256>>>(x, w);
    gemm_rows_kernel<<<dim3(4, 4, NCH), 256>>>();
    gemm_cols_kernel<<<dim3(4, 4, NCH), 256>>>(beta, out);
}

// round 7
// speedup vs baseline: 1.4605x; 1.4605x over previous
#include <cuda_runtime.h>
#include <math.h>

#define NB   8
#define CIN  96
#define COUT 192
#define C2   48
#define NCH  (NB*C2)     // 384 channels of 256x256

// Static scratch (allowed; no runtime allocation)
__device__ float  y_buf[NCH*256*256];   // pixel-shuffled conv output, ~100MB
__device__ float2 t_buf[NCH*256*256];   // row-lowpassed (complex), ~201MB

// ---------------------------------------------------------------------------
// complex helpers
// ---------------------------------------------------------------------------
__device__ __forceinline__ float2 cadd(float2 a, float2 b){ return make_float2(a.x+b.x, a.y+b.y); }
__device__ __forceinline__ float2 csub(float2 a, float2 b){ return make_float2(a.x-b.x, a.y-b.y); }
__device__ __forceinline__ float2 cmul(float2 a, float2 b){ return make_float2(a.x*b.x - a.y*b.y, a.x*b.y + a.y*b.x); }

// 8-point DFT in registers, natural order in/out. S=-1 forward, S=+1 inverse (unnormalized).
template<int S>
__device__ __forceinline__ void fft8r(float2 v[8]) {
    const float s = (float)S;
    const float r = 0.70710678118654752f;
    float2 w1 = make_float2( r, s*r);
    float2 w3 = make_float2(-r, s*r);
    // rot(a) = a * (s*i)  (forward: *-i, inverse: *+i)
    float2 t0=cadd(v[0],v[4]), t4=csub(v[0],v[4]);
    float2 t2=cadd(v[2],v[6]), t6=csub(v[2],v[6]);
    float2 t1=cadd(v[1],v[5]), t5=csub(v[1],v[5]);
    float2 t3=cadd(v[3],v[7]), t7=csub(v[3],v[7]);
    float2 rt6 = make_float2(-s*t6.y, s*t6.x);
    float2 rt7 = make_float2(-s*t7.y, s*t7.x);
    float2 u0=cadd(t0,t2), u2=csub(t0,t2);
    float2 u4=cadd(t4,rt6), u6=csub(t4,rt6);
    float2 u1=cadd(t1,t3), u3=csub(t1,t3);
    float2 u5=cadd(t5,rt7), u7=csub(t5,rt7);
    float2 ru3 = make_float2(-s*u3.y, s*u3.x);
    float2 wu5 = cmul(w1, u5);
    float2 wu7 = cmul(w3, u7);
    v[0]=cadd(u0,u1); v[4]=csub(u0,u1);
    v[2]=cadd(u2,ru3); v[6]=csub(u2,ru3);
    v[1]=cadd(u4,wu5); v[5]=csub(u4,wu5);
    v[3]=cadd(u6,wu7); v[7]=csub(u6,wu7);
}

__device__ __forceinline__ float2 shflxor2(float2 a, int d) {
    float2 r;
    r.x = __shfl_xor_sync(0xffffffffu, a.x, d);
    r.y = __shfl_xor_sync(0xffffffffu, a.y, d);
    return r;
}

// ---------------------------------------------------------------------------
// Half-band lowpass of a 256-point line held warp-wide:
//   v[j] = x[lane + 32*j]  ->  v[j] = lowpass(x)[lane + 32*j]
// lowpass = IDFT256( mask_{k in [0,64)U[192,256)} ( DFT256(x) ) ) / 256
// Decomposition: n = n1 + 32*n2 (n1=lane, n2=reg), k = k2 + 8*k1.
// Forward: reg-DFT8 (n2->k2) ; twiddle e^{-2pi i n1 k2/256} ; lane-DIF32 (n1->k1, bitrev in lanes).
// Mask depends on k1 only. Inverse mirrors.
// ---------------------------------------------------------------------------
__device__ __forceinline__ void lowpass256(float2 v[8], int lane) {
    const float PI = 3.14159265358979f;
    const float TW = 0.0245436926061703f;   // 2*pi/256

    // ---- forward ----
    fft8r<-1>(v);
    #pragma unroll
    for (int j = 1; j < 8; j++) {
        float sn, cs; __sincosf(-TW * (float)(lane * j), &sn, &cs);
        v[j] = cmul(v[j], make_float2(cs, sn));
    }
    #pragma unroll
    for (int d = 16; d >= 1; d >>= 1) {
        float sn, cs; __sincosf(-PI * (float)(lane & (d-1)) * (1.0f/(float)d), &sn, &cs);
        float2 tw = make_float2(cs, sn);
        bool hi = (lane & d) != 0;
        #pragma unroll
        for (int j = 0; j < 8; j++) {
            float2 o = shflxor2(v[j], d);
            v[j] = hi ? cmul(csub(o, v[j]), tw) : cadd(v[j], o);
        }
    }

    // ---- mask: lane holds k1 = bitrev5(lane); zero if 8 <= k1 < 24 ----
    unsigned k1 = __brev((unsigned)lane) >> 27;
    if (k1 >= 8u && k1 < 24u) {
        #pragma unroll
        for (int j = 0; j < 8; j++) v[j] = make_float2(0.f, 0.f);
    }

    // ---- inverse ----
    #pragma unroll
    for (int d = 1; d <= 16; d <<= 1) {
        float sn, cs; __sincosf(PI * (float)(lane & (d-1)) * (1.0f/(float)d), &sn, &cs);
        float2 tw = make_float2(cs, sn);
        bool hi = (lane & d) != 0;
        #pragma unroll
        for (int j = 0; j < 8; j++) {
            float2 a = v[j];
            if (hi) a = cmul(a, tw);
            float2 o = shflxor2(a, d);
            v[j] = hi ? csub(o, a) : cadd(a, o);
        }
    }
    #pragma unroll
    for (int j = 1; j < 8; j++) {
        float sn, cs; __sincosf(TW * (float)(lane * j), &sn, &cs);
        v[j] = cmul(v[j], make_float2(cs, sn));
    }
    fft8r<1>(v);
    #pragma unroll
    for (int j = 0; j < 8; j++) { v[j].x *= 0.00390625f; v[j].y *= 0.00390625f; }
}

// ---------------------------------------------------------------------------
// Conv 3x3 (pad 1) fused with pixel-shuffle write. (unchanged from R3)
// ---------------------------------------------------------------------------
__global__ __launch_bounds__(256, 4) void conv_ps_kernel(
    const float* __restrict__ x, const float* __restrict__ w)
{
    __shared__ float sx[8][18][20];
    __shared__ float sw_[32][8][9];

    int t    = threadIdx.x;
    int tile = blockIdx.x;
    int by   = (tile >> 3) * 16;
    int bx   = (tile & 7) * 16;
    int cob  = blockIdx.y * 32;
    int b    = blockIdx.z;
    int q    = t & 63;
    int cog  = t >> 6;
    int qy   = (q >> 3) * 2;
    int qx   = (q & 7) * 2;

    float acc[8][4];
    #pragma unroll
    for (int u = 0; u < 8; u++)
        #pragma unroll
        for (int p = 0; p < 4; p++) acc[u][p] = 0.f;

    for (int ci0 = 0; ci0 < CIN; ci0 += 8) {
        __syncthreads();
        for (int idx = t; idx < 8*18*18; idx += 256) {
            int ci  = idx / 324, rem = idx % 324;
            int iy  = rem / 18,  ix  = rem % 18;
            int gy  = by + iy - 1, gx = bx + ix - 1;
            float v = 0.f;
            if (gy >= 0 && gy < 128 && gx >= 0 && gx < 128)
                v = x[((b*CIN + ci0 + ci) * 128 + gy) * 128 + gx];
            sx[ci][iy][ix] = v;
        }
        for (int idx = t; idx < 32*8*9; idx += 256) {
            int co = idx / 72, rem = idx % 72;
            int ci = rem / 9,  tap = rem % 9;
            sw_[co][ci][tap] = w[((cob + co) * CIN + ci0 + ci) * 9 + tap];
        }
        __syncthreads();

        #pragma unroll 2
        for (int ci = 0; ci < 8; ci++) {
            #pragma unroll
            for (int tap = 0; tap < 9; tap++) {
                int ky = tap / 3, kx = tap % 3;
                float x00 = sx[ci][qy + ky    ][qx + kx    ];
                float x01 = sx[ci][qy + ky    ][qx + kx + 1];
                float x10 = sx[ci][qy + ky + 1][qx + kx    ];
                float x11 = sx[ci][qy + ky + 1][qx + kx + 1];
                #pragma unroll
                for (int u = 0; u < 8; u++) {
                    float wv = sw_[cog*8 + u][ci][tap];
                    acc[u][0] += wv * x00;
                    acc[u][1] += wv * x01;
                    acc[u][2] += wv * x10;
                    acc[u][3] += wv * x11;
                }
            }
        }
    }

    #pragma unroll
    for (int u = 0; u < 8; u++) {
        int co = cob + cog*8 + u;
        int c  = co >> 2;
        int i  = (co >> 1) & 1;
        int j  = co & 1;
        #pragma unroll
        for (int p = 0; p < 4; p++) {
            int py = by + qy + (p >> 1);
            int px = bx + qx + (p & 1);
            y_buf[((b*C2 + c) * 256 + (2*py + i)) * 256 + (2*px + j)] = acc[u][p];
        }
    }
}

// ---------------------------------------------------------------------------
// Row lowpass: one warp per row line; pure-register FFT.
// ---------------------------------------------------------------------------
__global__ __launch_bounds__(256) void lp_rows_kernel() {
    int warp = threadIdx.x >> 5, lane = threadIdx.x & 31;
    int line = blockIdx.x * 8 + warp;        // ch*256 + row
    const float* __restrict__ src = y_buf + line * 256;
    float2 v[8];
    #pragma unroll
    for (int j = 0; j < 8; j++) v[j] = make_float2(src[lane + 32*j], 0.f);
    lowpass256(v, lane);
    float2* dst = t_buf + line * 256;
    #pragma unroll
    for (int j = 0; j < 8; j++) dst[lane + 32*j] = v[j];
}

// ---------------------------------------------------------------------------
// Column lowpass + epilogue: 16-column tile staged in smem; each warp FFTs
// 2 columns; mag written back into smem; blended output coalesced.
//   out = beta*y + (1-2*beta)*|z|
// ---------------------------------------------------------------------------
__global__ __launch_bounds__(256) void lp_cols_kernel(
    const float* __restrict__ beta_ptr, float* __restrict__ out)
{
    __shared__ float2 st[256][17];           // padded: 2-way conflicts max

    int t  = threadIdx.x;
    int c0 = blockIdx.x * 16;
    int ch = blockIdx.y;
    int base = ch * 65536;

    for (int idx = t; idx < 4096; idx += 256) {
        int row = idx >> 4, c = idx & 15;
        st[row][c] = t_buf[base + row*256 + c0 + c];
    }
    __syncthreads();

    int warp = t >> 5, lane = t & 31;
    #pragma unroll
    for (int cc = 0; cc < 2; cc++) {
        int c = warp*2 + cc;
        float2 v[8];
        #pragma unroll
        for (int j = 0; j < 8; j++) v[j] = st[lane + 32*j][c];
        lowpass256(v, lane);
        #pragma unroll
        for (int j = 0; j < 8; j++)
            st[lane + 32*j][c].x = sqrtf(v[j].x*v[j].x + v[j].y*v[j].y);
    }
    __syncthreads();

    float beta = *beta_ptr;
    float cl   = 1.f - 2.f*beta;
    for (int idx = t; idx < 4096; idx += 256) {
        int row = idx >> 4, c = idx & 15;
        int o = base + row*256 + c0 + c;
        out[o] = beta * y_buf[o] + cl * st[row][c].x;
    }
}

// ---------------------------------------------------------------------------
extern "C" void kernel_launch(void* const* d_in, const int* in_sizes, int n_in,
                              void* d_out, int out_size)
{
    const float* x    = (const float*)d_in[0];
    const float* w    = (const float*)d_in[1];
    const float* beta = (const float*)d_in[2];
    float* out        = (float*)d_out;

    conv_ps_kernel<<<dim3(64, 6, NB), 256>>>(x, w);
    lp_rows_kernel<<<NCH*256/8, 256>>>();
    lp_cols_kernel<<<dim3(16, NCH), 256>>>(beta, out);
}

// round 11
// speedup vs baseline: 1.9020x; 1.3023x over previous
#include <cuda_runtime.h>
#include <cuda_bf16.h>
#include <math.h>
#include <stdint.h>

#define NB   8
#define CIN  96
#define COUT 192
#define C2   48
#define NCH  (NB*C2)     // 384 channels of 256x256

// Static scratch (allowed; no runtime allocation)
__device__ float  y_buf[NCH*256*256];            // pixel-shuffled conv output, ~100MB
__device__ float2 t_buf[NCH*256*256];            // row-lowpassed (complex), ~201MB
__device__ __nv_bfloat16 xth[NB*128*128*96];     // x transposed [b][y][x][96] hi
__device__ __nv_bfloat16 xtl[NB*128*128*96];     // lo
__device__ __nv_bfloat16 wprep[9*2*192*96];      // [tap][split][co][ci] bf16 split weights

// ===========================================================================
// helpers
// ===========================================================================
__device__ __forceinline__ uint32_t smem_to_u32(const void* p) {
    uint32_t a;
    asm("{ .reg .u64 t; cvta.to.shared.u64 t, %1; cvt.u32.u64 %0, t; }" : "=r"(a) : "l"(p));
    return a;
}

#define LDMX4(d, addr) \
    asm volatile("ldmatrix.sync.aligned.m8n8.x4.shared.b16 {%0,%1,%2,%3}, [%4];" \
        : "=r"((d)[0]), "=r"((d)[1]), "=r"((d)[2]), "=r"((d)[3]) : "r"(addr))

#define MMA16816(d, a, b0, b1) \
    asm volatile("mma.sync.aligned.m16n8k16.row.col.f32.bf16.bf16.f32 " \
        "{%0,%1,%2,%3}, {%4,%5,%6,%7}, {%8,%9}, {%0,%1,%2,%3};" \
        : "+f"((d)[0]), "+f"((d)[1]), "+f"((d)[2]), "+f"((d)[3]) \
        : "r"((a)[0]), "r"((a)[1]), "r"((a)[2]), "r"((a)[3]), "r"(b0), "r"(b1))

// ===========================================================================
// Prep: x NCHW fp32 -> xth/xtl [b][y][x][96] bf16 hi/lo (smem transpose)
// ===========================================================================
__global__ __launch_bounds__(256) void prep_x_kernel(const float* __restrict__ x) {
    __shared__ float s[96][65];
    int blk = blockIdx.x;                 // 8*128*2
    int half = blk & 1, y = (blk >> 1) & 127, b = blk >> 8;
    int x0 = half * 64;
    for (int i = threadIdx.x; i < 96*64; i += 256) {
        int ci = i >> 6, xx = i & 63;
        s[ci][xx] = x[((b*96 + ci)*128 + y)*128 + x0 + xx];
    }
    __syncthreads();
    for (int i = threadIdx.x; i < 1536; i += 256) {   // 64 px * 24 uint2
        int px = i / 24, q = i % 24, ci0 = q * 4;
        size_t base = ((size_t)((b*128 + y)*128 + x0 + px)) * 96 + ci0;
        unsigned short h[4], l[4];
        #pragma unroll
        for (int k = 0; k < 4; k++) {
            float v = s[ci0 + k][px];
            __nv_bfloat16 hb = __float2bfloat16(v);
            __nv_bfloat16 lb = __float2bfloat16(v - __bfloat162float(hb));
            h[k] = __bfloat16_as_ushort(hb);
            l[k] = __bfloat16_as_ushort(lb);
        }
        uint2 ho = make_uint2((uint32_t)h[0] | ((uint32_t)h[1] << 16), (uint32_t)h[2] | ((uint32_t)h[3] << 16));
        uint2 lo = make_uint2((uint32_t)l[0] | ((uint32_t)l[1] << 16), (uint32_t)l[2] | ((uint32_t)l[3] << 16));
        *(uint2*)(xth + base) = ho;
        *(uint2*)(xtl + base) = lo;
    }
}

// Prep weights: OIHW fp32 -> [tap][split][co][ci] bf16 hi/lo
__global__ __launch_bounds__(256) void prep_w_kernel(const float* __restrict__ w) {
    int i = blockIdx.x * 256 + threadIdx.x;     // 9*192*96
    if (i >= 9*192*96) return;
    int ci = i % 96, r = i / 96, co = r % 192, tap = r / 192;
    float v = w[(co*96 + ci)*9 + tap];
    __nv_bfloat16 hb = __float2bfloat16(v);
    __nv_bfloat16 lb = __float2bfloat16(v - __bfloat162float(hb));
    wprep[((tap*2 + 0)*192 + co)*96 + ci] = hb;
    wprep[((tap*2 + 1)*192 + co)*96 + ci] = lb;
}

// ===========================================================================
// Conv 3x3 implicit-GEMM on mma.sync bf16 (2-term split), fused pixel shuffle.
// CTA: one (batch, output row): M=128 px, N=192 co. 8 warps = 2(M) x 4(N),
// warp tile 64x48. A smem: [2 split][130 px_in][96 ci] stride 208.
// B smem: [2 split][192 co][96 ci] stride 208. ldmatrix conflict-free.
// ===========================================================================
#define AS_SZ   27040            // 130*208
#define BS_OFF  54080            // 2*AS_SZ
#define BS_SZ   39936            // 192*208
#define CONV_SMEM 133952         // BS_OFF + 2*BS_SZ

__global__ __launch_bounds__(256, 1) void conv_mma_kernel() {
    extern __shared__ char smem[];
    uint32_t sb = smem_to_u32(smem);
    int t = threadIdx.x, wid = t >> 5, l = t & 31;
    int blk = blockIdx.x;
    int b = blk >> 7, y = blk & 127;
    int wm = wid & 1, wn = wid >> 1;

    // lane constants for ldmatrix addressing
    int j  = l >> 3, r8 = l & 7;
    int aRow = (j & 1) * 8 + r8;          // A: row within m16 tile
    int aCol = (j >> 1) * 8;              // A: ci offset within k16
    int bRow = (j & 1) * 8 + r8;          // B: co within n16 pair
    int bCol = (j >> 1) * 8;              // B: ci offset within k16

    float acc[4][6][4];
    #pragma unroll
    for (int mi = 0; mi < 4; mi++)
        #pragma unroll
        for (int nf = 0; nf < 6; nf++)
            #pragma unroll
            for (int e = 0; e < 4; e++) acc[mi][nf][e] = 0.f;

    for (int tap = 0; tap < 9; tap++) {
        int ky = tap / 3, kx = tap % 3;
        __syncthreads();
        if (kx == 0) {
            int iy = y + ky - 1;
            bool rowok = (iy >= 0 && iy < 128);
            for (int i = t; i < 3120; i += 256) {       // 2 splits * 130 rows * 12 uint4
                int sp = i >= 1560; int i2 = sp ? i - 1560 : i;
                int rr = i2 / 12, u = i2 % 12;
                uint4 v = make_uint4(0u, 0u, 0u, 0u);
                int ix = rr - 1;
                if (rowok && ix >= 0 && ix < 128) {
                    const __nv_bfloat16* src = (sp ? xtl : xth) + ((size_t)((b*128 + iy)*128 + ix)) * 96;
                    v = ((const uint4*)src)[u];
                }
                *(uint4*)(smem + sp*AS_SZ + rr*208 + u*16) = v;
            }
        }
        for (int i = t; i < 4608; i += 256) {           // 2 splits * 192 rows * 12 uint4
            int sp = i >= 2304; int i2 = sp ? i - 2304 : i;
            int rr = i2 / 12, u = i2 % 12;
            uint4 v = ((const uint4*)(wprep + ((size_t)((tap*2 + sp)*192 + rr)) * 96))[u];
            *(uint4*)(smem + BS_OFF + sp*BS_SZ + rr*208 + u*16) = v;
        }
        __syncthreads();

        uint32_t aH = sb + (uint32_t)((wm*64 + kx + aRow) * 208 + aCol*2);
        uint32_t aL = aH + AS_SZ;
        uint32_t bH = sb + BS_OFF + (uint32_t)((wn*48 + bRow) * 208 + bCol*2);
        uint32_t bL = bH + BS_SZ;

        #pragma unroll
        for (int ks = 0; ks < 6; ks++) {
            uint32_t bh[3][4], bl[3][4];
            #pragma unroll
            for (int np = 0; np < 3; np++) {
                LDMX4(bh[np], bH + np*(16*208) + ks*32);
                LDMX4(bl[np], bL + np*(16*208) + ks*32);
            }
            #pragma unroll
            for (int mi = 0; mi < 4; mi++) {
                uint32_t ah[4], al[4];
                LDMX4(ah, aH + mi*(16*208) + ks*32);
                LDMX4(al, aL + mi*(16*208) + ks*32);
                #pragma unroll
                for (int np = 0; np < 3; np++) {
                    MMA16816(acc[mi][np*2+0], ah, bh[np][0], bh[np][2]);   // hh
                    MMA16816(acc[mi][np*2+1], ah, bh[np][1], bh[np][3]);
                    MMA16816(acc[mi][np*2+0], ah, bl[np][0], bl[np][2]);   // hl
                    MMA16816(acc[mi][np*2+1], ah, bl[np][1], bl[np][3]);
                    MMA16816(acc[mi][np*2+0], al, bh[np][0], bh[np][2]);   // lh
                    MMA16816(acc[mi][np*2+1], al, bh[np][1], bh[np][3]);
                }
            }
        }
    }

    // epilogue: pixel-shuffle write. acc rows = pixels, cols = co
    int gid = l >> 2, tid = l & 3;
    #pragma unroll
    for (int mi = 0; mi < 4; mi++) {
        #pragma unroll
        for (int nf = 0; nf < 6; nf++) {
            int co = wn*48 + nf*8 + 2*tid;              // even
            int ch = co >> 2, ii = (co >> 1) & 1;
            size_t rowbase = ((size_t)(b*C2 + ch)*256 + (2*y + ii)) * 256;
            int ox0 = wm*64 + mi*16 + gid;
            *(float2*)(y_buf + rowbase + 2*ox0)       = make_float2(acc[mi][nf][0], acc[mi][nf][1]);
            *(float2*)(y_buf + rowbase + 2*(ox0 + 8)) = make_float2(acc[mi][nf][2], acc[mi][nf][3]);
        }
    }
}

// ===========================================================================
// complex helpers + warp FFT lowpass (unchanged)
// ===========================================================================
__device__ __forceinline__ float2 cadd(float2 a, float2 b){ return make_float2(a.x+b.x, a.y+b.y); }
__device__ __forceinline__ float2 csub(float2 a, float2 b){ return make_float2(a.x-b.x, a.y-b.y); }
__device__ __forceinline__ float2 cmul(float2 a, float2 b){ return make_float2(a.x*b.x - a.y*b.y, a.x*b.y + a.y*b.x); }

template<int S>
__device__ __forceinline__ void fft8r(float2 v[8]) {
    const float s = (float)S;
    const float r = 0.70710678118654752f;
    float2 w1 = make_float2( r, s*r);
    float2 w3 = make_float2(-r, s*r);
    float2 t0=cadd(v[0],v[4]), t4=csub(v[0],v[4]);
    float2 t2=cadd(v[2],v[6]), t6=csub(v[2],v[6]);
    float2 t1=cadd(v[1],v[5]), t5=csub(v[1],v[5]);
    float2 t3=cadd(v[3],v[7]), t7=csub(v[3],v[7]);
    float2 rt6 = make_float2(-s*t6.y, s*t6.x);
    float2 rt7 = make_float2(-s*t7.y, s*t7.x);
    float2 u0=cadd(t0,t2), u2=csub(t0,t2);
    float2 u4=cadd(t4,rt6), u6=csub(t4,rt6);
    float2 u1=cadd(t1,t3), u3=csub(t1,t3);
    float2 u5=cadd(t5,rt7), u7=csub(t5,rt7);
    float2 ru3 = make_float2(-s*u3.y, s*u3.x);
    float2 wu5 = cmul(w1, u5);
    float2 wu7 = cmul(w3, u7);
    v[0]=cadd(u0,u1); v[4]=csub(u0,u1);
    v[2]=cadd(u2,ru3); v[6]=csub(u2,ru3);
    v[1]=cadd(u4,wu5); v[5]=csub(u4,wu5);
    v[3]=cadd(u6,wu7); v[7]=csub(u6,wu7);
}

__device__ __forceinline__ float2 shflxor2(float2 a, int d) {
    float2 r;
    r.x = __shfl_xor_sync(0xffffffffu, a.x, d);
    r.y = __shfl_xor_sync(0xffffffffu, a.y, d);
    return r;
}

__device__ __forceinline__ void lowpass256(float2 v[8], int lane) {
    const float PI = 3.14159265358979f;
    const float TW = 0.0245436926061703f;

    fft8r<-1>(v);
    #pragma unroll
    for (int j = 1; j < 8; j++) {
        float sn, cs; __sincosf(-TW * (float)(lane * j), &sn, &cs);
        v[j] = cmul(v[j], make_float2(cs, sn));
    }
    #pragma unroll
    for (int d = 16; d >= 1; d >>= 1) {
        float sn, cs; __sincosf(-PI * (float)(lane & (d-1)) * (1.0f/(float)d), &sn, &cs);
        float2 tw = make_float2(cs, sn);
        bool hi = (lane & d) != 0;
        #pragma unroll
        for (int j = 0; j < 8; j++) {
            float2 o = shflxor2(v[j], d);
            v[j] = hi ? cmul(csub(o, v[j]), tw) : cadd(v[j], o);
        }
    }
    unsigned k1 = __brev((unsigned)lane) >> 27;
    if (k1 >= 8u && k1 < 24u) {
        #pragma unroll
        for (int j = 0; j < 8; j++) v[j] = make_float2(0.f, 0.f);
    }
    #pragma unroll
    for (int d = 1; d <= 16; d <<= 1) {
        float sn, cs; __sincosf(PI * (float)(lane & (d-1)) * (1.0f/(float)d), &sn, &cs);
        float2 tw = make_float2(cs, sn);
        bool hi = (lane & d) != 0;
        #pragma unroll
        for (int j = 0; j < 8; j++) {
            float2 a = v[j];
            if (hi) a = cmul(a, tw);
            float2 o = shflxor2(a, d);
            v[j] = hi ? csub(o, a) : cadd(a, o);
        }
    }
    #pragma unroll
    for (int j = 1; j < 8; j++) {
        float sn, cs; __sincosf(TW * (float)(lane * j), &sn, &cs);
        v[j] = cmul(v[j], make_float2(cs, sn));
    }
    fft8r<1>(v);
    #pragma unroll
    for (int j = 0; j < 8; j++) { v[j].x *= 0.00390625f; v[j].y *= 0.00390625f; }
}

__global__ __launch_bounds__(256) void lp_rows_kernel() {
    int warp = threadIdx.x >> 5, lane = threadIdx.x & 31;
    int line = blockIdx.x * 8 + warp;
    const float* __restrict__ src = y_buf + (size_t)line * 256;
    float2 v[8];
    #pragma unroll
    for (int j = 0; j < 8; j++) v[j] = make_float2(src[lane + 32*j], 0.f);
    lowpass256(v, lane);
    float2* dst = t_buf + (size_t)line * 256;
    #pragma unroll
    for (int j = 0; j < 8; j++) dst[lane + 32*j] = v[j];
}

__global__ __launch_bounds__(256) void lp_cols_kernel(
    const float* __restrict__ beta_ptr, float* __restrict__ out)
{
    __shared__ float2 st[256][17];
    int t  = threadIdx.x;
    int c0 = blockIdx.x * 16;
    int ch = blockIdx.y;
    size_t base = (size_t)ch * 65536;

    for (int idx = t; idx < 4096; idx += 256) {
        int row = idx >> 4, c = idx & 15;
        st[row][c] = t_buf[base + row*256 + c0 + c];
    }
    __syncthreads();

    int warp = t >> 5, lane = t & 31;
    #pragma unroll
    for (int cc = 0; cc < 2; cc++) {
        int c = warp*2 + cc;
        float2 v[8];
        #pragma unroll
        for (int j = 0; j < 8; j++) v[j] = st[lane + 32*j][c];
        lowpass256(v, lane);
        #pragma unroll
        for (int j = 0; j < 8; j++)
            st[lane + 32*j][c].x = sqrtf(v[j].x*v[j].x + v[j].y*v[j].y);
    }
    __syncthreads();

    float beta = *beta_ptr;
    float cl   = 1.f - 2.f*beta;
    for (int idx = t; idx < 4096; idx += 256) {
        int row = idx >> 4, c = idx & 15;
        size_t o = base + row*256 + c0 + c;
        out[o] = beta * y_buf[o] + cl * st[row][c].x;
    }
}

// ---------------------------------------------------------------------------
extern "C" void kernel_launch(void* const* d_in, const int* in_sizes, int n_in,
                              void* d_out, int out_size)
{
    const float* x    = (const float*)d_in[0];
    const float* w    = (const float*)d_in[1];
    const float* beta = (const float*)d_in[2];
    float* out        = (float*)d_out;

    cudaFuncSetAttribute(conv_mma_kernel, cudaFuncAttributeMaxDynamicSharedMemorySize, CONV_SMEM);

    prep_x_kernel<<<NB*128*2, 256>>>(x);
    prep_w_kernel<<<(9*192*96 + 255)/256, 256>>>(w);
    conv_mma_kernel<<<NB*128, 256, CONV_SMEM>>>();
    lp_rows_kernel<<<NCH*256/8, 256>>>();
    lp_cols_kernel<<<dim3(16, NCH), 256>>>(beta, out);
}

// round 12
// speedup vs baseline: 2.9454x; 1.5486x over previous
#include <cuda_runtime.h>
#include <cuda_bf16.h>
#include <math.h>
#include <stdint.h>

#define NB   8
#define CIN  96
#define COUT 192
#define C2   48
#define NCH  (NB*C2)     // 384 channels of 256x256

// Static scratch (allowed; no runtime allocation)
__device__ float  y_buf[NCH*256*256];            // pixel-shuffled conv output, ~100MB
__device__ float2 t_buf[NCH*256*256];            // row-lowpassed (complex), ~201MB
__device__ __align__(16) __nv_bfloat16 xth[NB*128*128*96];   // x transposed [b][y][x][96] hi
__device__ __align__(16) __nv_bfloat16 xtl[NB*128*128*96];   // lo
__device__ __align__(16) __nv_bfloat16 wprep[9*2*192*96];    // [tap][split][co][ci]
__device__ float2 twtab[32][12];                 // per-lane twiddles: [0..6]=j, [7..11]=stage d=1,2,4,8,16

// ===========================================================================
// helpers
// ===========================================================================
__device__ __forceinline__ uint32_t smem_to_u32(const void* p) {
    uint32_t a;
    asm("{ .reg .u64 t; cvta.to.shared.u64 t, %1; cvt.u32.u64 %0, t; }" : "=r"(a) : "l"(p));
    return a;
}

#define LDMX4(d, addr) \
    asm volatile("ldmatrix.sync.aligned.m8n8.x4.shared.b16 {%0,%1,%2,%3}, [%4];" \
        : "=r"((d)[0]), "=r"((d)[1]), "=r"((d)[2]), "=r"((d)[3]) : "r"(addr))

#define MMA16816(d, a, b0, b1) \
    asm volatile("mma.sync.aligned.m16n8k16.row.col.f32.bf16.bf16.f32 " \
        "{%0,%1,%2,%3}, {%4,%5,%6,%7}, {%8,%9}, {%0,%1,%2,%3};" \
        : "+f"((d)[0]), "+f"((d)[1]), "+f"((d)[2]), "+f"((d)[3]) \
        : "r"((a)[0]), "r"((a)[1]), "r"((a)[2]), "r"((a)[3]), "r"(b0), "r"(b1))

#define CP_ASYNC16(dst, src, sz) \
    asm volatile("cp.async.cg.shared.global [%0], [%1], 16, %2;" :: "r"(dst), "l"(src), "r"(sz))
#define CP_COMMIT()   asm volatile("cp.async.commit_group;")
#define CP_WAIT_ALL() asm volatile("cp.async.wait_group 0;")

// ===========================================================================
// init twiddle table (lane-only):
//  slot j-1 (j=1..7): e^{-2*pi*i*lane*j/256}
//  slot 7+log2(d), d in {1,2,4,8,16}: e^{-i*pi*(lane&(d-1))/d}
// ===========================================================================
__global__ void init_tw_kernel() {
    int lane = threadIdx.x;
    const double PI = 3.14159265358979323846;
    for (int j = 1; j <= 7; j++) {
        double th = -2.0 * PI * (double)(lane * j) / 256.0;
        twtab[lane][j-1] = make_float2((float)cos(th), (float)sin(th));
    }
    int d = 1;
    for (int s = 0; s < 5; s++) {
        double th = -PI * (double)(lane & (d-1)) / (double)d;
        twtab[lane][7+s] = make_float2((float)cos(th), (float)sin(th));
        d <<= 1;
    }
}

// ===========================================================================
// Prep: x NCHW fp32 -> xth/xtl [b][y][x][96] bf16 hi/lo (smem transpose)
// ===========================================================================
__global__ __launch_bounds__(256) void prep_x_kernel(const float* __restrict__ x) {
    __shared__ float s[96][65];
    int blk = blockIdx.x;                 // 8*128*2
    int half = blk & 1, y = (blk >> 1) & 127, b = blk >> 8;
    int x0 = half * 64;
    for (int i = threadIdx.x; i < 96*64; i += 256) {
        int ci = i >> 6, xx = i & 63;
        s[ci][xx] = x[((b*96 + ci)*128 + y)*128 + x0 + xx];
    }
    __syncthreads();
    for (int i = threadIdx.x; i < 1536; i += 256) {   // 64 px * 24 uint2
        int px = i / 24, q = i % 24, ci0 = q * 4;
        size_t base = ((size_t)((b*128 + y)*128 + x0 + px)) * 96 + ci0;
        unsigned short h[4], l[4];
        #pragma unroll
        for (int k = 0; k < 4; k++) {
            float v = s[ci0 + k][px];
            __nv_bfloat16 hb = __float2bfloat16(v);
            __nv_bfloat16 lb = __float2bfloat16(v - __bfloat162float(hb));
            h[k] = __bfloat16_as_ushort(hb);
            l[k] = __bfloat16_as_ushort(lb);
        }
        uint2 ho = make_uint2((uint32_t)h[0] | ((uint32_t)h[1] << 16), (uint32_t)h[2] | ((uint32_t)h[3] << 16));
        uint2 lo = make_uint2((uint32_t)l[0] | ((uint32_t)l[1] << 16), (uint32_t)l[2] | ((uint32_t)l[3] << 16));
        *(uint2*)(xth + base) = ho;
        *(uint2*)(xtl + base) = lo;
    }
}

// Prep weights: OIHW fp32 -> [tap][split][co][ci] bf16 hi/lo
__global__ __launch_bounds__(256) void prep_w_kernel(const float* __restrict__ w) {
    int i = blockIdx.x * 256 + threadIdx.x;     // 9*192*96
    if (i >= 9*192*96) return;
    int ci = i % 96, r = i / 96, co = r % 192, tap = r / 192;
    float v = w[(co*96 + ci)*9 + tap];
    __nv_bfloat16 hb = __float2bfloat16(v);
    __nv_bfloat16 lb = __float2bfloat16(v - __bfloat162float(hb));
    wprep[((tap*2 + 0)*192 + co)*96 + ci] = hb;
    wprep[((tap*2 + 1)*192 + co)*96 + ci] = lb;
}

// ===========================================================================
// Conv 3x3 implicit-GEMM on mma.sync bf16 (2-term split), cp.async pipelined.
// CTA: one (batch, output row): M=128 px, N=192 co. 8 warps = 2(M) x 4(N).
// smem: A [2 split][130][208] at 0 (54080); B double buffer at 54080,
//       each buffer [2 split][192][208] (79872). Total 213824.
// ===========================================================================
#define AS_SZ   27040            // 130*208
#define B_OFF   54080            // 2*AS_SZ
#define BS_SZ   39936            // 192*208
#define BBUF    79872            // 2*BS_SZ
#define CONV_SMEM 213824         // B_OFF + 2*BBUF

__global__ __launch_bounds__(256, 1) void conv_mma_kernel() {
    extern __shared__ char smem[];
    uint32_t sb = smem_to_u32(smem);
    int t = threadIdx.x, wid = t >> 5, l = t & 31;
    int blk = blockIdx.x;
    int b = blk >> 7, y = blk & 127;
    int wm = wid & 1, wn = wid >> 1;

    // ---- async loaders ----
    auto loadB = [&](int tap, int bb) {
        const char* base = (const char*)wprep + (size_t)tap * (2*192*96*2);
        #pragma unroll 4
        for (int i = t; i < 4608; i += 256) {           // 2 splits * 192 rows * 12 x 16B
            int sp = i >= 2304; int i2 = i - sp*2304;
            int rr = i2 / 12, u = i2 % 12;
            uint32_t dst = sb + B_OFF + bb*BBUF + sp*BS_SZ + rr*208 + u*16;
            const char* src = base + ((size_t)(sp*192 + rr))*192 + u*16;
            CP_ASYNC16(dst, src, 16);
        }
    };
    auto loadA = [&](int ky) {
        int iy = y + ky - 1;
        bool rowok = (iy >= 0 && iy < 128);
        int iyc = iy < 0 ? 0 : (iy > 127 ? 127 : iy);
        #pragma unroll 4
        for (int i = t; i < 3120; i += 256) {           // 2 splits * 130 rows * 12 x 16B
            int sp = i >= 1560; int i2 = i - sp*1560;
            int rr = i2 / 12, u = i2 % 12;
            int ix = rr - 1;
            bool ok = rowok && ix >= 0 && ix < 128;
            int ixc = ix < 0 ? 0 : (ix > 127 ? 127 : ix);
            uint32_t dst = sb + sp*AS_SZ + rr*208 + u*16;
            const char* src = (const char*)(sp ? xtl : xth)
                            + ((size_t)((b*128 + iyc)*128 + ixc))*192 + u*16;
            CP_ASYNC16(dst, src, ok ? 16 : 0);
        }
    };

    // lane constants for ldmatrix addressing
    int j  = l >> 3, r8 = l & 7;
    int aRow = (j & 1) * 8 + r8;
    int aCol = (j >> 1) * 8;
    int bRow = (j & 1) * 8 + r8;
    int bCol = (j >> 1) * 8;

    float acc[4][6][4];
    #pragma unroll
    for (int mi = 0; mi < 4; mi++)
        #pragma unroll
        for (int nf = 0; nf < 6; nf++)
            #pragma unroll
            for (int e = 0; e < 4; e++) acc[mi][nf][e] = 0.f;

    loadA(0);
    loadB(0, 0);
    CP_COMMIT();
    CP_WAIT_ALL();
    __syncthreads();

    for (int tap = 0; tap < 9; tap++) {
        int kx = tap % 3, bb = tap & 1;

        // prefetch next tap's B into the other buffer (overlaps MMA below)
        if (tap < 8) { loadB(tap + 1, 1 - bb); CP_COMMIT(); }

        uint32_t aH = sb + (uint32_t)((wm*64 + kx + aRow) * 208 + aCol*2);
        uint32_t aL = aH + AS_SZ;
        uint32_t bH = sb + B_OFF + bb*BBUF + (uint32_t)((wn*48 + bRow) * 208 + bCol*2);
        uint32_t bL = bH + BS_SZ;

        #pragma unroll
        for (int ks = 0; ks < 6; ks++) {
            uint32_t bh[3][4], bl[3][4];
            #pragma unroll
            for (int np = 0; np < 3; np++) {
                LDMX4(bh[np], bH + np*(16*208) + ks*32);
                LDMX4(bl[np], bL + np*(16*208) + ks*32);
            }
            #pragma unroll
            for (int mi = 0; mi < 4; mi++) {
                uint32_t ah[4], al[4];
                LDMX4(ah, aH + mi*(16*208) + ks*32);
                LDMX4(al, aL + mi*(16*208) + ks*32);
                #pragma unroll
                for (int np = 0; np < 3; np++) {
                    MMA16816(acc[mi][np*2+0], ah, bh[np][0], bh[np][2]);   // hh
                    MMA16816(acc[mi][np*2+1], ah, bh[np][1], bh[np][3]);
                    MMA16816(acc[mi][np*2+0], ah, bl[np][0], bl[np][2]);   // hl
                    MMA16816(acc[mi][np*2+1], ah, bl[np][1], bl[np][3]);
                    MMA16816(acc[mi][np*2+0], al, bh[np][0], bh[np][2]);   // lh
                    MMA16816(acc[mi][np*2+1], al, bh[np][1], bh[np][3]);
                }
            }
        }

        if (tap < 8) {
            if (kx == 2) {
                __syncthreads();                 // all warps done reading A
                loadA(tap/3 + 1);
                CP_COMMIT();
            }
            CP_WAIT_ALL();
            __syncthreads();
        }
    }

    // epilogue: pixel-shuffle write. acc rows = pixels, cols = co
    int gid = l >> 2, tid = l & 3;
    #pragma unroll
    for (int mi = 0; mi < 4; mi++) {
        #pragma unroll
        for (int nf = 0; nf < 6; nf++) {
            int co = wn*48 + nf*8 + 2*tid;
            int ch = co >> 2, ii = (co >> 1) & 1;
            size_t rowbase = ((size_t)(b*C2 + ch)*256 + (2*y + ii)) * 256;
            int ox0 = wm*64 + mi*16 + gid;
            *(float2*)(y_buf + rowbase + 2*ox0)       = make_float2(acc[mi][nf][0], acc[mi][nf][1]);
            *(float2*)(y_buf + rowbase + 2*(ox0 + 8)) = make_float2(acc[mi][nf][2], acc[mi][nf][3]);
        }
    }
}

// ===========================================================================
// complex helpers + warp FFT lowpass (twiddles from table)
// ===========================================================================
__device__ __forceinline__ float2 cadd(float2 a, float2 b){ return make_float2(a.x+b.x, a.y+b.y); }
__device__ __forceinline__ float2 csub(float2 a, float2 b){ return make_float2(a.x-b.x, a.y-b.y); }
__device__ __forceinline__ float2 cmul(float2 a, float2 b){ return make_float2(a.x*b.x - a.y*b.y, a.x*b.y + a.y*b.x); }
__device__ __forceinline__ float2 cmulc(float2 a, float2 b){ return make_float2(a.x*b.x + a.y*b.y, a.y*b.x - a.x*b.y); }  // a * conj(b)

template<int S>
__device__ __forceinline__ void fft8r(float2 v[8]) {
    const float s = (float)S;
    const float r = 0.70710678118654752f;
    float2 w1 = make_float2( r, s*r);
    float2 w3 = make_float2(-r, s*r);
    float2 t0=cadd(v[0],v[4]), t4=csub(v[0],v[4]);
    float2 t2=cadd(v[2],v[6]), t6=csub(v[2],v[6]);
    float2 t1=cadd(v[1],v[5]), t5=csub(v[1],v[5]);
    float2 t3=cadd(v[3],v[7]), t7=csub(v[3],v[7]);
    float2 rt6 = make_float2(-s*t6.y, s*t6.x);
    float2 rt7 = make_float2(-s*t7.y, s*t7.x);
    float2 u0=cadd(t0,t2), u2=csub(t0,t2);
    float2 u4=cadd(t4,rt6), u6=csub(t4,rt6);
    float2 u1=cadd(t1,t3), u3=csub(t1,t3);
    float2 u5=cadd(t5,rt7), u7=csub(t5,rt7);
    float2 ru3 = make_float2(-s*u3.y, s*u3.x);
    float2 wu5 = cmul(w1, u5);
    float2 wu7 = cmul(w3, u7);
    v[0]=cadd(u0,u1); v[4]=csub(u0,u1);
    v[2]=cadd(u2,ru3); v[6]=csub(u2,ru3);
    v[1]=cadd(u4,wu5); v[5]=csub(u4,wu5);
    v[3]=cadd(u6,wu7); v[7]=csub(u6,wu7);
}

__device__ __forceinline__ float2 shflxor2(float2 a, int d) {
    float2 r;
    r.x = __shfl_xor_sync(0xffffffffu, a.x, d);
    r.y = __shfl_xor_sync(0xffffffffu, a.y, d);
    return r;
}

// tw[0..6] = e^{-2pi i lane j/256}, tw[7+log2 d] = e^{-i pi (lane&(d-1))/d}
__device__ __forceinline__ void lowpass256(float2 v[8], int lane, const float2 tw[12]) {
    // ---- forward ----
    fft8r<-1>(v);
    #pragma unroll
    for (int j = 1; j < 8; j++) v[j] = cmul(v[j], tw[j-1]);
    #pragma unroll
    for (int s = 4; s >= 0; s--) {
        int d = 1 << s;
        float2 w = tw[7 + s];
        bool hi = (lane & d) != 0;
        #pragma unroll
        for (int j = 0; j < 8; j++) {
            float2 o = shflxor2(v[j], d);
            v[j] = hi ? cmul(csub(o, v[j]), w) : cadd(v[j], o);
        }
    }
    // ---- mask: lane holds k1 = bitrev5(lane); zero if 8 <= k1 < 24 ----
    unsigned k1 = __brev((unsigned)lane) >> 27;
    if (k1 >= 8u && k1 < 24u) {
        #pragma unroll
        for (int j = 0; j < 8; j++) v[j] = make_float2(0.f, 0.f);
    }
    // ---- inverse (conjugated twiddles) ----
    #pragma unroll
    for (int s = 0; s <= 4; s++) {
        int d = 1 << s;
        float2 w = tw[7 + s];
        bool hi = (lane & d) != 0;
        #pragma unroll
        for (int j = 0; j < 8; j++) {
            float2 a = v[j];
            if (hi) a = cmulc(a, w);
            float2 o = shflxor2(a, d);
            v[j] = hi ? csub(o, a) : cadd(a, o);
        }
    }
    #pragma unroll
    for (int j = 1; j < 8; j++) v[j] = cmulc(v[j], tw[j-1]);
    fft8r<1>(v);
    #pragma unroll
    for (int j = 0; j < 8; j++) { v[j].x *= 0.00390625f; v[j].y *= 0.00390625f; }
}

__global__ __launch_bounds__(256) void lp_rows_kernel() {
    int warp = threadIdx.x >> 5, lane = threadIdx.x & 31;
    float2 tw[12];
    #pragma unroll
    for (int i = 0; i < 12; i++) tw[i] = twtab[lane][i];
    int line = blockIdx.x * 8 + warp;
    const float* __restrict__ src = y_buf + (size_t)line * 256;
    float2 v[8];
    #pragma unroll
    for (int j = 0; j < 8; j++) v[j] = make_float2(src[lane + 32*j], 0.f);
    lowpass256(v, lane, tw);
    float2* dst = t_buf + (size_t)line * 256;
    #pragma unroll
    for (int j = 0; j < 8; j++) dst[lane + 32*j] = v[j];
}

__global__ __launch_bounds__(256) void lp_cols_kernel(
    const float* __restrict__ beta_ptr, float* __restrict__ out)
{
    __shared__ float2 st[256][17];
    int t  = threadIdx.x;
    int c0 = blockIdx.x * 16;
    int ch = blockIdx.y;
    size_t base = (size_t)ch * 65536;
    int warp = t >> 5, lane = t & 31;
    float2 tw[12];
    #pragma unroll
    for (int i = 0; i < 12; i++) tw[i] = twtab[lane][i];

    for (int idx = t; idx < 4096; idx += 256) {
        int row = idx >> 4, c = idx & 15;
        st[row][c] = t_buf[base + row*256 + c0 + c];
    }
    __syncthreads();

    #pragma unroll
    for (int cc = 0; cc < 2; cc++) {
        int c = warp*2 + cc;
        float2 v[8];
        #pragma unroll
        for (int j = 0; j < 8; j++) v[j] = st[lane + 32*j][c];
        lowpass256(v, lane, tw);
        #pragma unroll
        for (int j = 0; j < 8; j++)
            st[lane + 32*j][c].x = sqrtf(v[j].x*v[j].x + v[j].y*v[j].y);
    }
    __syncthreads();

    float beta = *beta_ptr;
    float cl   = 1.f - 2.f*beta;
    for (int idx = t; idx < 4096; idx += 256) {
        int row = idx >> 4, c = idx & 15;
        size_t o = base + row*256 + c0 + c;
        out[o] = beta * y_buf[o] + cl * st[row][c].x;
    }
}

// ---------------------------------------------------------------------------
extern "C" void kernel_launch(void* const* d_in, const int* in_sizes, int n_in,
                              void* d_out, int out_size)
{
    const float* x    = (const float*)d_in[0];
    const float* w    = (const float*)d_in[1];
    const float* beta = (const float*)d_in[2];
    float* out        = (float*)d_out;

    cudaFuncSetAttribute(conv_mma_kernel, cudaFuncAttributeMaxDynamicSharedMemorySize, CONV_SMEM);

    init_tw_kernel<<<1, 32>>>();
    prep_x_kernel<<<NB*128*2, 256>>>(x);
    prep_w_kernel<<<(9*192*96 + 255)/256, 256>>>(w);
    conv_mma_kernel<<<NB*128, 256, CONV_SMEM>>>();
    lp_rows_kernel<<<NCH*256/8, 256>>>();
    lp_cols_kernel<<<dim3(16, NCH), 256>>>(beta, out);
}

// round 13
// speedup vs baseline: 3.0513x; 1.0359x over previous
#include <cuda_runtime.h>
#include <cuda_bf16.h>
#include <math.h>
#include <stdint.h>

#define NB   8
#define CIN  96
#define COUT 192
#define C2   48
#define NCH  (NB*C2)     // 384 channels of 256x256

// Static scratch (allowed; no runtime allocation)
__device__ float  y_buf[NCH*256*256];            // pixel-shuffled conv output, ~100MB
__device__ float2 t_buf[NCH*256*256];            // row-lowpassed (complex), ~201MB
__device__ __align__(16) __nv_bfloat16 xth[NB*128*128*96];   // x transposed [b][y][x][96] hi
__device__ __align__(16) __nv_bfloat16 xtl[NB*128*128*96];   // lo
__device__ __align__(16) __nv_bfloat16 wprep[9*2*192*96];    // [tap][split][co][ci]
__device__ float2 twtab[32][12];                 // per-lane twiddles: [0..6]=j, [7..11]=stage d=1,2,4,8,16

// ===========================================================================
// helpers
// ===========================================================================
__device__ __forceinline__ uint32_t smem_to_u32(const void* p) {
    uint32_t a;
    asm("{ .reg .u64 t; cvta.to.shared.u64 t, %1; cvt.u32.u64 %0, t; }" : "=r"(a) : "l"(p));
    return a;
}

#define LDMX4(d, addr) \
    asm volatile("ldmatrix.sync.aligned.m8n8.x4.shared.b16 {%0,%1,%2,%3}, [%4];" \
        : "=r"((d)[0]), "=r"((d)[1]), "=r"((d)[2]), "=r"((d)[3]) : "r"(addr))

#define MMA16816(d, a, b0, b1) \
    asm volatile("mma.sync.aligned.m16n8k16.row.col.f32.bf16.bf16.f32 " \
        "{%0,%1,%2,%3}, {%4,%5,%6,%7}, {%8,%9}, {%0,%1,%2,%3};" \
        : "+f"((d)[0]), "+f"((d)[1]), "+f"((d)[2]), "+f"((d)[3]) \
        : "r"((a)[0]), "r"((a)[1]), "r"((a)[2]), "r"((a)[3]), "r"(b0), "r"(b1))

#define CP_ASYNC16(dst, src, sz) \
    asm volatile("cp.async.cg.shared.global [%0], [%1], 16, %2;" :: "r"(dst), "l"(src), "r"(sz))
#define CP_COMMIT()   asm volatile("cp.async.commit_group;")
#define CP_WAIT_ALL() asm volatile("cp.async.wait_group 0;")

// ===========================================================================
// init twiddle table (lane-only)
// ===========================================================================
__global__ void init_tw_kernel() {
    int lane = threadIdx.x;
    const double PI = 3.14159265358979323846;
    for (int j = 1; j <= 7; j++) {
        double th = -2.0 * PI * (double)(lane * j) / 256.0;
        twtab[lane][j-1] = make_float2((float)cos(th), (float)sin(th));
    }
    int d = 1;
    for (int s = 0; s < 5; s++) {
        double th = -PI * (double)(lane & (d-1)) / (double)d;
        twtab[lane][7+s] = make_float2((float)cos(th), (float)sin(th));
        d <<= 1;
    }
}

// ===========================================================================
// Prep: x NCHW fp32 -> xth/xtl [b][y][x][96] bf16 hi/lo (smem transpose)
// ===========================================================================
__global__ __launch_bounds__(256) void prep_x_kernel(const float* __restrict__ x) {
    __shared__ float s[96][65];
    int blk = blockIdx.x;                 // 8*128*2
    int half = blk & 1, y = (blk >> 1) & 127, b = blk >> 8;
    int x0 = half * 64;
    for (int i = threadIdx.x; i < 96*64; i += 256) {
        int ci = i >> 6, xx = i & 63;
        s[ci][xx] = x[((b*96 + ci)*128 + y)*128 + x0 + xx];
    }
    __syncthreads();
    for (int i = threadIdx.x; i < 1536; i += 256) {   // 64 px * 24 uint2
        int px = i / 24, q = i % 24, ci0 = q * 4;
        size_t base = ((size_t)((b*128 + y)*128 + x0 + px)) * 96 + ci0;
        unsigned short h[4], l[4];
        #pragma unroll
        for (int k = 0; k < 4; k++) {
            float v = s[ci0 + k][px];
            __nv_bfloat16 hb = __float2bfloat16(v);
            __nv_bfloat16 lb = __float2bfloat16(v - __bfloat162float(hb));
            h[k] = __bfloat16_as_ushort(hb);
            l[k] = __bfloat16_as_ushort(lb);
        }
        uint2 ho = make_uint2((uint32_t)h[0] | ((uint32_t)h[1] << 16), (uint32_t)h[2] | ((uint32_t)h[3] << 16));
        uint2 lo = make_uint2((uint32_t)l[0] | ((uint32_t)l[1] << 16), (uint32_t)l[2] | ((uint32_t)l[3] << 16));
        *(uint2*)(xth + base) = ho;
        *(uint2*)(xtl + base) = lo;
    }
}

// Prep weights: OIHW fp32 -> [tap][split][co][ci] bf16 hi/lo
__global__ __launch_bounds__(256) void prep_w_kernel(const float* __restrict__ w) {
    int i = blockIdx.x * 256 + threadIdx.x;     // 9*192*96
    if (i >= 9*192*96) return;
    int ci = i % 96, r = i / 96, co = r % 192, tap = r / 192;
    float v = w[(co*96 + ci)*9 + tap];
    __nv_bfloat16 hb = __float2bfloat16(v);
    __nv_bfloat16 lb = __float2bfloat16(v - __bfloat162float(hb));
    wprep[((tap*2 + 0)*192 + co)*96 + ci] = hb;
    wprep[((tap*2 + 1)*192 + co)*96 + ci] = lb;
}

// ===========================================================================
// Conv 3x3 implicit-GEMM on mma.sync bf16 (2-term split), cp.async pipelined.
// CTA: (batch,row) x n-chunk: M=128 px, N=64 co. 8 warps = 4(M) x 2(N),
// warp tile 32x32. 2 CTAs/SM (107KB smem, <=128 regs).
// smem: A [2 split][130][208] at 0 (54080); B double buffer at 54080,
//       each buffer [2 split][64][208] (26624). Total 107328.
// ===========================================================================
#define AS_SZ   27040            // 130*208
#define B_OFF   54080            // 2*AS_SZ
#define BS_SZ   13312            // 64*208
#define BBUF    26624            // 2*BS_SZ
#define CONV_SMEM 107328         // B_OFF + 2*BBUF

__global__ __launch_bounds__(256, 2) void conv_mma_kernel() {
    extern __shared__ char smem[];
    uint32_t sb = smem_to_u32(smem);
    int t = threadIdx.x, wid = t >> 5, l = t & 31;
    int blk = blockIdx.x;
    int b = blk >> 7, y = blk & 127;
    int ny = blockIdx.y;                  // n chunk 0..2 (co base = ny*64)
    int wm = wid & 3, wn = wid >> 2;

    // ---- async loaders ----
    auto loadB = [&](int tap, int bb) {
        const char* base = (const char*)wprep
            + ((size_t)(tap*2*192 + ny*64)) * 192;      // [tap][sp=0][ny*64][0], sp stride = 192*192B
        #pragma unroll 4
        for (int i = t; i < 1536; i += 256) {           // 2 splits * 64 rows * 12 x 16B
            int sp = i >= 768; int i2 = i - sp*768;
            int rr = i2 / 12, u = i2 % 12;
            uint32_t dst = sb + B_OFF + bb*BBUF + sp*BS_SZ + rr*208 + u*16;
            const char* src = base + ((size_t)(sp*192 + rr))*192 + u*16;
            CP_ASYNC16(dst, src, 16);
        }
    };
    auto loadA = [&](int ky) {
        int iy = y + ky - 1;
        bool rowok = (iy >= 0 && iy < 128);
        int iyc = iy < 0 ? 0 : (iy > 127 ? 127 : iy);
        #pragma unroll 4
        for (int i = t; i < 3120; i += 256) {           // 2 splits * 130 rows * 12 x 16B
            int sp = i >= 1560; int i2 = i - sp*1560;
            int rr = i2 / 12, u = i2 % 12;
            int ix = rr - 1;
            bool ok = rowok && ix >= 0 && ix < 128;
            int ixc = ix < 0 ? 0 : (ix > 127 ? 127 : ix);
            uint32_t dst = sb + sp*AS_SZ + rr*208 + u*16;
            const char* src = (const char*)(sp ? xtl : xth)
                            + ((size_t)((b*128 + iyc)*128 + ixc))*192 + u*16;
            CP_ASYNC16(dst, src, ok ? 16 : 0);
        }
    };

    // lane constants for ldmatrix addressing
    int j  = l >> 3, r8 = l & 7;
    int aRow = (j & 1) * 8 + r8;
    int aCol = (j >> 1) * 8;
    int bRow = (j & 1) * 8 + r8;
    int bCol = (j >> 1) * 8;

    float acc[2][4][4];
    #pragma unroll
    for (int mi = 0; mi < 2; mi++)
        #pragma unroll
        for (int nf = 0; nf < 4; nf++)
            #pragma unroll
            for (int e = 0; e < 4; e++) acc[mi][nf][e] = 0.f;

    loadA(0);
    loadB(0, 0);
    CP_COMMIT();
    CP_WAIT_ALL();
    __syncthreads();

    for (int tap = 0; tap < 9; tap++) {
        int kx = tap % 3, bb = tap & 1;

        // prefetch next tap's B into the other buffer (overlaps MMA below)
        if (tap < 8) { loadB(tap + 1, 1 - bb); CP_COMMIT(); }

        uint32_t aH = sb + (uint32_t)((wm*32 + kx + aRow) * 208 + aCol*2);
        uint32_t aL = aH + AS_SZ;
        uint32_t bH = sb + B_OFF + bb*BBUF + (uint32_t)((wn*32 + bRow) * 208 + bCol*2);
        uint32_t bL = bH + BS_SZ;

        #pragma unroll
        for (int ks = 0; ks < 6; ks++) {
            uint32_t bh[2][4], bl[2][4];
            #pragma unroll
            for (int np = 0; np < 2; np++) {
                LDMX4(bh[np], bH + np*(16*208) + ks*32);
                LDMX4(bl[np], bL + np*(16*208) + ks*32);
            }
            #pragma unroll
            for (int mi = 0; mi < 2; mi++) {
                uint32_t ah[4], al[4];
                LDMX4(ah, aH + mi*(16*208) + ks*32);
                LDMX4(al, aL + mi*(16*208) + ks*32);
                #pragma unroll
                for (int np = 0; np < 2; np++) {
                    MMA16816(acc[mi][np*2+0], ah, bh[np][0], bh[np][2]);   // hh
                    MMA16816(acc[mi][np*2+1], ah, bh[np][1], bh[np][3]);
                    MMA16816(acc[mi][np*2+0], ah, bl[np][0], bl[np][2]);   // hl
                    MMA16816(acc[mi][np*2+1], ah, bl[np][1], bl[np][3]);
                    MMA16816(acc[mi][np*2+0], al, bh[np][0], bh[np][2]);   // lh
                    MMA16816(acc[mi][np*2+1], al, bh[np][1], bh[np][3]);
                }
            }
        }

        if (tap < 8) {
            if (kx == 2) {
                __syncthreads();                 // all warps done reading A
                loadA(tap/3 + 1);
                CP_COMMIT();
            }
            CP_WAIT_ALL();
            __syncthreads();
        }
    }

    // epilogue: pixel-shuffle write. acc rows = pixels, cols = co
    int gid = l >> 2, tid = l & 3;
    #pragma unroll
    for (int mi = 0; mi < 2; mi++) {
        #pragma unroll
        for (int nf = 0; nf < 4; nf++) {
            int co = ny*64 + wn*32 + nf*8 + 2*tid;
            int ch = co >> 2, ii = (co >> 1) & 1;
            size_t rowbase = ((size_t)(b*C2 + ch)*256 + (2*y + ii)) * 256;
            int ox0 = wm*32 + mi*16 + gid;
            *(float2*)(y_buf + rowbase + 2*ox0)       = make_float2(acc[mi][nf][0], acc[mi][nf][1]);
            *(float2*)(y_buf + rowbase + 2*(ox0 + 8)) = make_float2(acc[mi][nf][2], acc[mi][nf][3]);
        }
    }
}

// ===========================================================================
// complex helpers + warp FFT lowpass (twiddles from table)
// ===========================================================================
__device__ __forceinline__ float2 cadd(float2 a, float2 b){ return make_float2(a.x+b.x, a.y+b.y); }
__device__ __forceinline__ float2 csub(float2 a, float2 b){ return make_float2(a.x-b.x, a.y-b.y); }
__device__ __forceinline__ float2 cmul(float2 a, float2 b){ return make_float2(a.x*b.x - a.y*b.y, a.x*b.y + a.y*b.x); }
__device__ __forceinline__ float2 cmulc(float2 a, float2 b){ return make_float2(a.x*b.x + a.y*b.y, a.y*b.x - a.x*b.y); }  // a * conj(b)

template<int S>
__device__ __forceinline__ void fft8r(float2 v[8]) {
    const float s = (float)S;
    const float r = 0.70710678118654752f;
    float2 w1 = make_float2( r, s*r);
    float2 w3 = make_float2(-r, s*r);
    float2 t0=cadd(v[0],v[4]), t4=csub(v[0],v[4]);
    float2 t2=cadd(v[2],v[6]), t6=csub(v[2],v[6]);
    float2 t1=cadd(v[1],v[5]), t5=csub(v[1],v[5]);
    float2 t3=cadd(v[3],v[7]), t7=csub(v[3],v[7]);
    float2 rt6 = make_float2(-s*t6.y, s*t6.x);
    float2 rt7 = make_float2(-s*t7.y, s*t7.x);
    float2 u0=cadd(t0,t2), u2=csub(t0,t2);
    float2 u4=cadd(t4,rt6), u6=csub(t4,rt6);
    float2 u1=cadd(t1,t3), u3=csub(t1,t3);
    float2 u5=cadd(t5,rt7), u7=csub(t5,rt7);
    float2 ru3 = make_float2(-s*u3.y, s*u3.x);
    float2 wu5 = cmul(w1, u5);
    float2 wu7 = cmul(w3, u7);
    v[0]=cadd(u0,u1); v[4]=csub(u0,u1);
    v[2]=cadd(u2,ru3); v[6]=csub(u2,ru3);
    v[1]=cadd(u4,wu5); v[5]=csub(u4,wu5);
    v[3]=cadd(u6,wu7); v[7]=csub(u6,wu7);
}

__device__ __forceinline__ float2 shflxor2(float2 a, int d) {
    float2 r;
    r.x = __shfl_xor_sync(0xffffffffu, a.x, d);
    r.y = __shfl_xor_sync(0xffffffffu, a.y, d);
    return r;
}

// tw[0..6] = e^{-2pi i lane j/256}, tw[7+log2 d] = e^{-i pi (lane&(d-1))/d}
__device__ __forceinline__ void lowpass256(float2 v[8], int lane, const float2 tw[12]) {
    // ---- forward ----
    fft8r<-1>(v);
    #pragma unroll
    for (int j = 1; j < 8; j++) v[j] = cmul(v[j], tw[j-1]);
    #pragma unroll
    for (int s = 4; s >= 0; s--) {
        int d = 1 << s;
        float2 w = tw[7 + s];
        bool hi = (lane & d) != 0;
        #pragma unroll
        for (int j = 0; j < 8; j++) {
            float2 o = shflxor2(v[j], d);
            v[j] = hi ? cmul(csub(o, v[j]), w) : cadd(v[j], o);
        }
    }
    // ---- mask: lane holds k1 = bitrev5(lane); zero if 8 <= k1 < 24 ----
    unsigned k1 = __brev((unsigned)lane) >> 27;
    if (k1 >= 8u && k1 < 24u) {
        #pragma unroll
        for (int j = 0; j < 8; j++) v[j] = make_float2(0.f, 0.f);
    }
    // ---- inverse (conjugated twiddles) ----
    #pragma unroll
    for (int s = 0; s <= 4; s++) {
        int d = 1 << s;
        float2 w = tw[7 + s];
        bool hi = (lane & d) != 0;
        #pragma unroll
        for (int j = 0; j < 8; j++) {
            float2 a = v[j];
            if (hi) a = cmulc(a, w);
            float2 o = shflxor2(a, d);
            v[j] = hi ? csub(o, a) : cadd(a, o);
        }
    }
    #pragma unroll
    for (int j = 1; j < 8; j++) v[j] = cmulc(v[j], tw[j-1]);
    fft8r<1>(v);
    #pragma unroll
    for (int j = 0; j < 8; j++) { v[j].x *= 0.00390625f; v[j].y *= 0.00390625f; }
}

__global__ __launch_bounds__(256) void lp_rows_kernel() {
    int warp = threadIdx.x >> 5, lane = threadIdx.x & 31;
    float2 tw[12];
    #pragma unroll
    for (int i = 0; i < 12; i++) tw[i] = twtab[lane][i];
    int line = blockIdx.x * 8 + warp;
    const float* __restrict__ src = y_buf + (size_t)line * 256;
    float2 v[8];
    #pragma unroll
    for (int j = 0; j < 8; j++) v[j] = make_float2(src[lane + 32*j], 0.f);
    lowpass256(v, lane, tw);
    float2* dst = t_buf + (size_t)line * 256;
    #pragma unroll
    for (int j = 0; j < 8; j++) dst[lane + 32*j] = v[j];
}

__global__ __launch_bounds__(256) void lp_cols_kernel(
    const float* __restrict__ beta_ptr, float* __restrict__ out)
{
    __shared__ float2 st[256][17];
    int t  = threadIdx.x;
    int c0 = blockIdx.x * 16;
    int ch = blockIdx.y;
    size_t base = (size_t)ch * 65536;
    int warp = t >> 5, lane = t & 31;
    float2 tw[12];
    #pragma unroll
    for (int i = 0; i < 12; i++) tw[i] = twtab[lane][i];

    for (int idx = t; idx < 4096; idx += 256) {
        int row = idx >> 4, c = idx & 15;
        st[row][c] = t_buf[base + row*256 + c0 + c];
    }
    __syncthreads();

    #pragma unroll
    for (int cc = 0; cc < 2; cc++) {
        int c = warp*2 + cc;
        float2 v[8];
        #pragma unroll
        for (int j = 0; j < 8; j++) v[j] = st[lane + 32*j][c];
        lowpass256(v, lane, tw);
        #pragma unroll
        for (int j = 0; j < 8; j++)
            st[lane + 32*j][c].x = sqrtf(v[j].x*v[j].x + v[j].y*v[j].y);
    }
    __syncthreads();

    float beta = *beta_ptr;
    float cl   = 1.f - 2.f*beta;
    for (int idx = t; idx < 4096; idx += 256) {
        int row = idx >> 4, c = idx & 15;
        size_t o = base + row*256 + c0 + c;
        out[o] = beta * y_buf[o] + cl * st[row][c].x;
    }
}

// ---------------------------------------------------------------------------
extern "C" void kernel_launch(void* const* d_in, const int* in_sizes, int n_in,
                              void* d_out, int out_size)
{
    const float* x    = (const float*)d_in[0];
    const float* w    = (const float*)d_in[1];
    const float* beta = (const float*)d_in[2];
    float* out        = (float*)d_out;

    cudaFuncSetAttribute(conv_mma_kernel, cudaFuncAttributeMaxDynamicSharedMemorySize, CONV_SMEM);

    init_tw_kernel<<<1, 32>>>();
    prep_x_kernel<<<NB*128*2, 256>>>(x);
    prep_w_kernel<<<(9*192*96 + 255)/256, 256>>>(w);
    conv_mma_kernel<<<dim3(NB*128, 3), 256, CONV_SMEM>>>();
    lp_rows_kernel<<<NCH*256/8, 256>>>();
    lp_cols_kernel<<<dim3(16, NCH), 256>>>(beta, out);
}

// round 14
// speedup vs baseline: 3.1303x; 1.0259x over previous
#include <cuda_runtime.h>
#include <cuda_bf16.h>
#include <math.h>
#include <stdint.h>

#define NB   8
#define CIN  96
#define COUT 192
#define C2   48
#define NCH  (NB*C2)     // 384 channels of 256x256

// Static scratch (allowed; no runtime allocation)
__device__ float  y_buf[NCH*256*256];            // pixel-shuffled conv output, ~100MB
__device__ float  t_buf[NCH*256*256];            // row-lowpassed (REAL now), ~100MB
__device__ __align__(16) __nv_bfloat16 xth[NB*128*128*96];   // x transposed [b][y][x][96] hi
__device__ __align__(16) __nv_bfloat16 xtl[NB*128*128*96];   // lo
__device__ __align__(16) __nv_bfloat16 wprep[9*2*192*96];    // [tap][split][co][ci]
__device__ float2 twtab[32][12];                 // per-lane twiddles
__device__ float2 p_buf[NCH*256];                // p[m2] = sum_m1 y*i^m1
__device__ float2 q_buf[NCH*256];                // q[m1] = sum_m2 y*i^m2
__device__ float2 h_buf[NCH*256];                // h = lowpass_s(p)/256
__device__ float2 g_buf[NCH*256];                // g = lowpass_s(q)/256
__device__ float2 c_buf[NCH];                    // c = sum_m2 p*i^m2 / 65536

// ===========================================================================
// helpers
// ===========================================================================
__device__ __forceinline__ uint32_t smem_to_u32(const void* p) {
    uint32_t a;
    asm("{ .reg .u64 t; cvta.to.shared.u64 t, %1; cvt.u32.u64 %0, t; }" : "=r"(a) : "l"(p));
    return a;
}

#define LDMX4(d, addr) \
    asm volatile("ldmatrix.sync.aligned.m8n8.x4.shared.b16 {%0,%1,%2,%3}, [%4];" \
        : "=r"((d)[0]), "=r"((d)[1]), "=r"((d)[2]), "=r"((d)[3]) : "r"(addr))

#define MMA16816(d, a, b0, b1) \
    asm volatile("mma.sync.aligned.m16n8k16.row.col.f32.bf16.bf16.f32 " \
        "{%0,%1,%2,%3}, {%4,%5,%6,%7}, {%8,%9}, {%0,%1,%2,%3};" \
        : "+f"((d)[0]), "+f"((d)[1]), "+f"((d)[2]), "+f"((d)[3]) \
        : "r"((a)[0]), "r"((a)[1]), "r"((a)[2]), "r"((a)[3]), "r"(b0), "r"(b1))

#define CP_ASYNC16(dst, src, sz) \
    asm volatile("cp.async.cg.shared.global [%0], [%1], 16, %2;" :: "r"(dst), "l"(src), "r"(sz))
#define CP_COMMIT()   asm volatile("cp.async.commit_group;")
#define CP_WAIT_ALL() asm volatile("cp.async.wait_group 0;")

// ===========================================================================
// init twiddle table (lane-only)
// ===========================================================================
__global__ void init_tw_kernel() {
    int lane = threadIdx.x;
    const double PI = 3.14159265358979323846;
    for (int j = 1; j <= 7; j++) {
        double th = -2.0 * PI * (double)(lane * j) / 256.0;
        twtab[lane][j-1] = make_float2((float)cos(th), (float)sin(th));
    }
    int d = 1;
    for (int s = 0; s < 5; s++) {
        double th = -PI * (double)(lane & (d-1)) / (double)d;
        twtab[lane][7+s] = make_float2((float)cos(th), (float)sin(th));
        d <<= 1;
    }
}

// ===========================================================================
// Prep: x NCHW fp32 -> xth/xtl [b][y][x][96] bf16 hi/lo (smem transpose)
// ===========================================================================
__global__ __launch_bounds__(256) void prep_x_kernel(const float* __restrict__ x) {
    __shared__ float s[96][65];
    int blk = blockIdx.x;                 // 8*128*2
    int half = blk & 1, y = (blk >> 1) & 127, b = blk >> 8;
    int x0 = half * 64;
    for (int i = threadIdx.x; i < 96*64; i += 256) {
        int ci = i >> 6, xx = i & 63;
        s[ci][xx] = x[((b*96 + ci)*128 + y)*128 + x0 + xx];
    }
    __syncthreads();
    for (int i = threadIdx.x; i < 1536; i += 256) {   // 64 px * 24 uint2
        int px = i / 24, q = i % 24, ci0 = q * 4;
        size_t base = ((size_t)((b*128 + y)*128 + x0 + px)) * 96 + ci0;
        unsigned short h[4], l[4];
        #pragma unroll
        for (int k = 0; k < 4; k++) {
            float v = s[ci0 + k][px];
            __nv_bfloat16 hb = __float2bfloat16(v);
            __nv_bfloat16 lb = __float2bfloat16(v - __bfloat162float(hb));
            h[k] = __bfloat16_as_ushort(hb);
            l[k] = __bfloat16_as_ushort(lb);
        }
        uint2 ho = make_uint2((uint32_t)h[0] | ((uint32_t)h[1] << 16), (uint32_t)h[2] | ((uint32_t)h[3] << 16));
        uint2 lo = make_uint2((uint32_t)l[0] | ((uint32_t)l[1] << 16), (uint32_t)l[2] | ((uint32_t)l[3] << 16));
        *(uint2*)(xth + base) = ho;
        *(uint2*)(xtl + base) = lo;
    }
}

// Prep weights: OIHW fp32 -> [tap][split][co][ci] bf16 hi/lo
__global__ __launch_bounds__(256) void prep_w_kernel(const float* __restrict__ w) {
    int i = blockIdx.x * 256 + threadIdx.x;     // 9*192*96
    if (i >= 9*192*96) return;
    int ci = i % 96, r = i / 96, co = r % 192, tap = r / 192;
    float v = w[(co*96 + ci)*9 + tap];
    __nv_bfloat16 hb = __float2bfloat16(v);
    __nv_bfloat16 lb = __float2bfloat16(v - __bfloat162float(hb));
    wprep[((tap*2 + 0)*192 + co)*96 + ci] = hb;
    wprep[((tap*2 + 1)*192 + co)*96 + ci] = lb;
}

// ===========================================================================
// Conv 3x3 implicit-GEMM (unchanged from R13)
// ===========================================================================
#define AS_SZ   27040            // 130*208
#define B_OFF   54080            // 2*AS_SZ
#define BS_SZ   13312            // 64*208
#define BBUF    26624            // 2*BS_SZ
#define CONV_SMEM 107328         // B_OFF + 2*BBUF

__global__ __launch_bounds__(256, 2) void conv_mma_kernel() {
    extern __shared__ char smem[];
    uint32_t sb = smem_to_u32(smem);
    int t = threadIdx.x, wid = t >> 5, l = t & 31;
    int blk = blockIdx.x;
    int b = blk >> 7, y = blk & 127;
    int ny = blockIdx.y;
    int wm = wid & 3, wn = wid >> 2;

    auto loadB = [&](int tap, int bb) {
        const char* base = (const char*)wprep + ((size_t)(tap*2*192 + ny*64)) * 192;
        #pragma unroll 4
        for (int i = t; i < 1536; i += 256) {
            int sp = i >= 768; int i2 = i - sp*768;
            int rr = i2 / 12, u = i2 % 12;
            uint32_t dst = sb + B_OFF + bb*BBUF + sp*BS_SZ + rr*208 + u*16;
            const char* src = base + ((size_t)(sp*192 + rr))*192 + u*16;
            CP_ASYNC16(dst, src, 16);
        }
    };
    auto loadA = [&](int ky) {
        int iy = y + ky - 1;
        bool rowok = (iy >= 0 && iy < 128);
        int iyc = iy < 0 ? 0 : (iy > 127 ? 127 : iy);
        #pragma unroll 4
        for (int i = t; i < 3120; i += 256) {
            int sp = i >= 1560; int i2 = i - sp*1560;
            int rr = i2 / 12, u = i2 % 12;
            int ix = rr - 1;
            bool ok = rowok && ix >= 0 && ix < 128;
            int ixc = ix < 0 ? 0 : (ix > 127 ? 127 : ix);
            uint32_t dst = sb + sp*AS_SZ + rr*208 + u*16;
            const char* src = (const char*)(sp ? xtl : xth)
                            + ((size_t)((b*128 + iyc)*128 + ixc))*192 + u*16;
            CP_ASYNC16(dst, src, ok ? 16 : 0);
        }
    };

    int j  = l >> 3, r8 = l & 7;
    int aRow = (j & 1) * 8 + r8;
    int aCol = (j >> 1) * 8;
    int bRow = (j & 1) * 8 + r8;
    int bCol = (j >> 1) * 8;

    float acc[2][4][4];
    #pragma unroll
    for (int mi = 0; mi < 2; mi++)
        #pragma unroll
        for (int nf = 0; nf < 4; nf++)
            #pragma unroll
            for (int e = 0; e < 4; e++) acc[mi][nf][e] = 0.f;

    loadA(0);
    loadB(0, 0);
    CP_COMMIT();
    CP_WAIT_ALL();
    __syncthreads();

    for (int tap = 0; tap < 9; tap++) {
        int kx = tap % 3, bb = tap & 1;
        if (tap < 8) { loadB(tap + 1, 1 - bb); CP_COMMIT(); }

        uint32_t aH = sb + (uint32_t)((wm*32 + kx + aRow) * 208 + aCol*2);
        uint32_t aL = aH + AS_SZ;
        uint32_t bH = sb + B_OFF + bb*BBUF + (uint32_t)((wn*32 + bRow) * 208 + bCol*2);
        uint32_t bL = bH + BS_SZ;

        #pragma unroll
        for (int ks = 0; ks < 6; ks++) {
            uint32_t bh[2][4], bl[2][4];
            #pragma unroll
            for (int np = 0; np < 2; np++) {
                LDMX4(bh[np], bH + np*(16*208) + ks*32);
                LDMX4(bl[np], bL + np*(16*208) + ks*32);
            }
            #pragma unroll
            for (int mi = 0; mi < 2; mi++) {
                uint32_t ah[4], al[4];
                LDMX4(ah, aH + mi*(16*208) + ks*32);
                LDMX4(al, aL + mi*(16*208) + ks*32);
                #pragma unroll
                for (int np = 0; np < 2; np++) {
                    MMA16816(acc[mi][np*2+0], ah, bh[np][0], bh[np][2]);
                    MMA16816(acc[mi][np*2+1], ah, bh[np][1], bh[np][3]);
                    MMA16816(acc[mi][np*2+0], ah, bl[np][0], bl[np][2]);
                    MMA16816(acc[mi][np*2+1], ah, bl[np][1], bl[np][3]);
                    MMA16816(acc[mi][np*2+0], al, bh[np][0], bh[np][2]);
                    MMA16816(acc[mi][np*2+1], al, bh[np][1], bh[np][3]);
                }
            }
        }

        if (tap < 8) {
            if (kx == 2) {
                __syncthreads();
                loadA(tap/3 + 1);
                CP_COMMIT();
            }
            CP_WAIT_ALL();
            __syncthreads();
        }
    }

    int gid = l >> 2, tid = l & 3;
    #pragma unroll
    for (int mi = 0; mi < 2; mi++) {
        #pragma unroll
        for (int nf = 0; nf < 4; nf++) {
            int co = ny*64 + wn*32 + nf*8 + 2*tid;
            int ch = co >> 2, ii = (co >> 1) & 1;
            size_t rowbase = ((size_t)(b*C2 + ch)*256 + (2*y + ii)) * 256;
            int ox0 = wm*32 + mi*16 + gid;
            *(float2*)(y_buf + rowbase + 2*ox0)       = make_float2(acc[mi][nf][0], acc[mi][nf][1]);
            *(float2*)(y_buf + rowbase + 2*(ox0 + 8)) = make_float2(acc[mi][nf][2], acc[mi][nf][3]);
        }
    }
}

// ===========================================================================
// complex helpers + SYMMETRIC-mask warp FFT lowpass
// mask S keeps k in [0,63] U [193,255]  (= [-63,63]); the extra k=192 bin
// of the reference mask is handled by rank-1 corrections (p,q,h,g,c).
// ===========================================================================
__device__ __forceinline__ float2 cadd(float2 a, float2 b){ return make_float2(a.x+b.x, a.y+b.y); }
__device__ __forceinline__ float2 csub(float2 a, float2 b){ return make_float2(a.x-b.x, a.y-b.y); }
__device__ __forceinline__ float2 cmul(float2 a, float2 b){ return make_float2(a.x*b.x - a.y*b.y, a.x*b.y + a.y*b.x); }
__device__ __forceinline__ float2 cmulc(float2 a, float2 b){ return make_float2(a.x*b.x + a.y*b.y, a.y*b.x - a.x*b.y); }

template<int S>
__device__ __forceinline__ void fft8r(float2 v[8]) {
    const float s = (float)S;
    const float r = 0.70710678118654752f;
    float2 w1 = make_float2( r, s*r);
    float2 w3 = make_float2(-r, s*r);
    float2 t0=cadd(v[0],v[4]), t4=csub(v[0],v[4]);
    float2 t2=cadd(v[2],v[6]), t6=csub(v[2],v[6]);
    float2 t1=cadd(v[1],v[5]), t5=csub(v[1],v[5]);
    float2 t3=cadd(v[3],v[7]), t7=csub(v[3],v[7]);
    float2 rt6 = make_float2(-s*t6.y, s*t6.x);
    float2 rt7 = make_float2(-s*t7.y, s*t7.x);
    float2 u0=cadd(t0,t2), u2=csub(t0,t2);
    float2 u4=cadd(t4,rt6), u6=csub(t4,rt6);
    float2 u1=cadd(t1,t3), u3=csub(t1,t3);
    float2 u5=cadd(t5,rt7), u7=csub(t5,rt7);
    float2 ru3 = make_float2(-s*u3.y, s*u3.x);
    float2 wu5 = cmul(w1, u5);
    float2 wu7 = cmul(w3, u7);
    v[0]=cadd(u0,u1); v[4]=csub(u0,u1);
    v[2]=cadd(u2,ru3); v[6]=csub(u2,ru3);
    v[1]=cadd(u4,wu5); v[5]=csub(u4,wu5);
    v[3]=cadd(u6,wu7); v[7]=csub(u6,wu7);
}

__device__ __forceinline__ float2 shflxor2(float2 a, int d) {
    float2 r;
    r.x = __shfl_xor_sync(0xffffffffu, a.x, d);
    r.y = __shfl_xor_sync(0xffffffffu, a.y, d);
    return r;
}

__device__ __forceinline__ void lowpass_s(float2 v[8], int lane, const float2 tw[12]) {
    fft8r<-1>(v);
    #pragma unroll
    for (int j = 1; j < 8; j++) v[j] = cmul(v[j], tw[j-1]);
    #pragma unroll
    for (int s = 4; s >= 0; s--) {
        int d = 1 << s;
        float2 w = tw[7 + s];
        bool hi = (lane & d) != 0;
        #pragma unroll
        for (int j = 0; j < 8; j++) {
            float2 o = shflxor2(v[j], d);
            v[j] = hi ? cmul(csub(o, v[j]), w) : cadd(v[j], o);
        }
    }
    // symmetric mask: lane holds k1 = bitrev5(lane), reg j holds k2
    // zero k1 in [8,24); for k1==24 zero only k2==0 (k=192)
    unsigned k1 = __brev((unsigned)lane) >> 27;
    if (k1 >= 8u && k1 < 24u) {
        #pragma unroll
        for (int j = 0; j < 8; j++) v[j] = make_float2(0.f, 0.f);
    } else if (k1 == 24u) {
        v[0] = make_float2(0.f, 0.f);
    }
    #pragma unroll
    for (int s = 0; s <= 4; s++) {
        int d = 1 << s;
        float2 w = tw[7 + s];
        bool hi = (lane & d) != 0;
        #pragma unroll
        for (int j = 0; j < 8; j++) {
            float2 a = v[j];
            if (hi) a = cmulc(a, w);
            float2 o = shflxor2(a, d);
            v[j] = hi ? csub(o, a) : cadd(a, o);
        }
    }
    #pragma unroll
    for (int j = 1; j < 8; j++) v[j] = cmulc(v[j], tw[j-1]);
    fft8r<1>(v);
    #pragma unroll
    for (int j = 0; j < 8; j++) { v[j].x *= 0.00390625f; v[j].y *= 0.00390625f; }
}

// s * i^n  and  z * (-i)^n
__device__ __forceinline__ float2 imul_pow(float s, int n) {
    switch (n & 3) {
        case 0:  return make_float2(s, 0.f);
        case 1:  return make_float2(0.f, s);
        case 2:  return make_float2(-s, 0.f);
        default: return make_float2(0.f, -s);
    }
}
__device__ __forceinline__ float2 rot_negi(float2 z, int n) {
    switch (n & 3) {
        case 0:  return z;
        case 1:  return make_float2(z.y, -z.x);
        case 2:  return make_float2(-z.x, -z.y);
        default: return make_float2(-z.y, z.x);
    }
}

// ===========================================================================
// p kernel: p[ch][m2] = sum_m1 y[ch][m1][m2] * i^m1   (CTA per channel)
// ===========================================================================
__global__ __launch_bounds__(256) void p_kernel() {
    int ch = blockIdx.x, m2 = threadIdx.x;
    const float* __restrict__ Y = y_buf + (size_t)ch * 65536;
    float pr = 0.f, pi = 0.f;
    #pragma unroll 4
    for (int m1 = 0; m1 < 256; m1 += 4) {
        pr += Y[(m1+0)*256 + m2];
        pi += Y[(m1+1)*256 + m2];
        pr -= Y[(m1+2)*256 + m2];
        pi -= Y[(m1+3)*256 + m2];
    }
    p_buf[ch*256 + m2] = make_float2(pr, pi);
}

// ===========================================================================
// Row lowpass (packed pairs) + q reduction.
// warp handles rows (2u, 2u+1) as complex a+ib; S-filter is real so
// Re->row 2u, Im->row 2u+1. Also q[m1] = sum_m2 y*i^m2 (weight lane-only).
// ===========================================================================
__global__ __launch_bounds__(256) void lp_rows_kernel() {
    int warp = threadIdx.x >> 5, lane = threadIdx.x & 31;
    float2 tw[12];
    #pragma unroll
    for (int i = 0; i < 12; i++) tw[i] = twtab[lane][i];

    int gu = blockIdx.x * 8 + warp;          // 0 .. NCH*128-1
    int ch = gu >> 7, r0 = (gu & 127) * 2;
    const float* __restrict__ srcA = y_buf + ((size_t)ch*256 + r0) * 256;
    const float* __restrict__ srcB = srcA + 256;

    float2 v[8];
    float sa = 0.f, sb = 0.f;
    #pragma unroll
    for (int j = 0; j < 8; j++) {
        float a = srcA[lane + 32*j], b = srcB[lane + 32*j];
        v[j] = make_float2(a, b);
        sa += a; sb += b;
    }
    // q reduction: q[r] = sum_lane (sum_j row[lane+32j]) * i^lane
    float2 ca = imul_pow(sa, lane), cb = imul_pow(sb, lane);
    #pragma unroll
    for (int d = 16; d >= 1; d >>= 1) {
        ca.x += __shfl_xor_sync(0xffffffffu, ca.x, d);
        ca.y += __shfl_xor_sync(0xffffffffu, ca.y, d);
        cb.x += __shfl_xor_sync(0xffffffffu, cb.x, d);
        cb.y += __shfl_xor_sync(0xffffffffu, cb.y, d);
    }
    if (lane == 0) {
        q_buf[ch*256 + r0]     = ca;
        q_buf[ch*256 + r0 + 1] = cb;
    }

    lowpass_s(v, lane, tw);

    float* dstA = t_buf + ((size_t)ch*256 + r0) * 256;
    float* dstB = dstA + 256;
    #pragma unroll
    for (int j = 0; j < 8; j++) {
        dstA[lane + 32*j] = v[j].x;
        dstB[lane + 32*j] = v[j].y;
    }
}

// ===========================================================================
// hgc kernel: per channel (one warp): h = lowpass_s(p)/256, g = lowpass_s(q)/256,
// c = (sum_m2 p[m2]*i^m2)/65536.
// ===========================================================================
__global__ __launch_bounds__(256) void hgc_kernel() {
    int warp = threadIdx.x >> 5, lane = threadIdx.x & 31;
    int ch = blockIdx.x * 8 + warp;
    float2 tw[12];
    #pragma unroll
    for (int i = 0; i < 12; i++) tw[i] = twtab[lane][i];

    float2 v[8];
    #pragma unroll
    for (int j = 0; j < 8; j++) v[j] = p_buf[ch*256 + lane + 32*j];

    // c reduction (weight i^(lane+32j) = i^lane)
    float2 s = make_float2(0.f, 0.f);
    #pragma unroll
    for (int j = 0; j < 8; j++) s = cadd(s, v[j]);
    float2 w;  // s * i^lane
    switch (lane & 3) {
        case 0:  w = s; break;
        case 1:  w = make_float2(-s.y, s.x); break;
        case 2:  w = make_float2(-s.x, -s.y); break;
        default: w = make_float2(s.y, -s.x); break;
    }
    #pragma unroll
    for (int d = 16; d >= 1; d >>= 1) {
        w.x += __shfl_xor_sync(0xffffffffu, w.x, d);
        w.y += __shfl_xor_sync(0xffffffffu, w.y, d);
    }
    if (lane == 0) c_buf[ch] = make_float2(w.x * 1.52587890625e-5f, w.y * 1.52587890625e-5f);

    lowpass_s(v, lane, tw);
    #pragma unroll
    for (int j = 0; j < 8; j++)
        h_buf[ch*256 + lane + 32*j] = make_float2(v[j].x * 0.00390625f, v[j].y * 0.00390625f);

    #pragma unroll
    for (int j = 0; j < 8; j++) v[j] = q_buf[ch*256 + lane + 32*j];
    lowpass_s(v, lane, tw);
    #pragma unroll
    for (int j = 0; j < 8; j++)
        g_buf[ch*256 + lane + 32*j] = make_float2(v[j].x * 0.00390625f, v[j].y * 0.00390625f);
}

// ===========================================================================
// Column lowpass (packed col pairs) + rank-1 corrections + blend epilogue.
// z = z_ss + (-i)^{n1}*(h[n2] + c*(-i)^{n2}) + g[n1]*(-i)^{n2}
// out = beta*y + (1-2*beta)*|z|
// ===========================================================================
__global__ __launch_bounds__(256) void lp_cols_kernel(
    const float* __restrict__ beta_ptr, float* __restrict__ out)
{
    __shared__ float st[256][17];
    int t  = threadIdx.x;
    int c0 = blockIdx.x * 16;
    int ch = blockIdx.y;
    size_t base = (size_t)ch * 65536;
    int warp = t >> 5, lane = t & 31;
    float2 tw[12];
    #pragma unroll
    for (int i = 0; i < 12; i++) tw[i] = twtab[lane][i];

    for (int idx = t; idx < 4096; idx += 256) {
        int row = idx >> 4, c = idx & 15;
        st[row][c] = t_buf[base + row*256 + c0 + c];
    }
    __syncthreads();

    {
        int n2A = c0 + 2*warp, n2B = n2A + 1;
        float2 v[8];
        #pragma unroll
        for (int j = 0; j < 8; j++)
            v[j] = make_float2(st[lane + 32*j][2*warp], st[lane + 32*j][2*warp + 1]);
        lowpass_s(v, lane, tw);

        float2 cc_ = c_buf[ch];
        float2 giA = rot_negi(make_float2(1.f, 0.f), n2A);
        float2 giB = rot_negi(make_float2(1.f, 0.f), n2B);
        float2 hcA = cadd(h_buf[ch*256 + n2A], cmul(cc_, giA));
        float2 hcB = cadd(h_buf[ch*256 + n2B], cmul(cc_, giB));

        #pragma unroll
        for (int j = 0; j < 8; j++) {
            int n1 = lane + 32*j;
            float2 g = g_buf[ch*256 + n1];
            float2 corrA = cadd(rot_negi(hcA, lane), cmul(g, giA));
            float2 corrB = cadd(rot_negi(hcB, lane), cmul(g, giB));
            float zAr = v[j].x + corrA.x, zAi = corrA.y;
            float zBr = v[j].y + corrB.x, zBi = corrB.y;
            st[n1][2*warp]     = sqrtf(zAr*zAr + zAi*zAi);
            st[n1][2*warp + 1] = sqrtf(zBr*zBr + zBi*zBi);
        }
    }
    __syncthreads();

    float beta = *beta_ptr;
    float cl   = 1.f - 2.f*beta;
    for (int idx = t; idx < 4096; idx += 256) {
        int row = idx >> 4, c = idx & 15;
        size_t o = base + row*256 + c0 + c;
        out[o] = beta * y_buf[o] + cl * st[row][c];
    }
}

// ---------------------------------------------------------------------------
extern "C" void kernel_launch(void* const* d_in, const int* in_sizes, int n_in,
                              void* d_out, int out_size)
{
    const float* x    = (const float*)d_in[0];
    const float* w    = (const float*)d_in[1];
    const float* beta = (const float*)d_in[2];
    float* out        = (float*)d_out;

    cudaFuncSetAttribute(conv_mma_kernel, cudaFuncAttributeMaxDynamicSharedMemorySize, CONV_SMEM);

    init_tw_kernel<<<1, 32>>>();
    prep_x_kernel<<<NB*128*2, 256>>>(x);
    prep_w_kernel<<<(9*192*96 + 255)/256, 256>>>(w);
    conv_mma_kernel<<<dim3(NB*128, 3), 256, CONV_SMEM>>>();
    p_kernel<<<NCH, 256>>>();
    lp_rows_kernel<<<NCH*128/8, 256>>>();
    hgc_kernel<<<NCH/8, 256>>>();
    lp_cols_kernel<<<dim3(16, NCH), 256>>>(beta, out);
}

// round 16
// speedup vs baseline: 3.6409x; 1.1631x over previous
#include <cuda_runtime.h>
#include <cuda_fp16.h>
#include <math.h>
#include <stdint.h>

#define NB   8
#define CIN  96
#define COUT 192
#define C2   48
#define NCH  (NB*C2)     // 384 channels of 256x256

// Static scratch (allowed; no runtime allocation)
__device__ float  y_buf[NCH*256*256];            // pixel-shuffled conv output, ~100MB
__device__ float  t_buf[NCH*256*256];            // row-lowpassed (REAL), ~100MB
__device__ __align__(16) __half xth[NB*128*128*96];          // x transposed [b][y][x][96] fp16
__device__ __align__(16) __half wprep[9*2*192*96];           // [tap][{wh,ew}][co][ci]
__device__ float2 twtab[32][12];                 // per-lane twiddles
__device__ float2 p_buf[NCH*256];                // p[m2] = sum_m1 y*i^m1
__device__ float2 q_buf[NCH*256];                // q[m1] = sum_m2 y*i^m2
__device__ float2 h_buf[NCH*256];                // h = lowpass_s(p)/256
__device__ float2 g_buf[NCH*256];                // g = lowpass_s(q)/256
__device__ float2 c_buf[NCH];                    // c = sum_m2 p*i^m2 / 65536

// ===========================================================================
// helpers
// ===========================================================================
__device__ __forceinline__ uint32_t smem_to_u32(const void* p) {
    uint32_t a;
    asm("{ .reg .u64 t; cvta.to.shared.u64 t, %1; cvt.u32.u64 %0, t; }" : "=r"(a) : "l"(p));
    return a;
}

#define LDMX4(d, addr) \
    asm volatile("ldmatrix.sync.aligned.m8n8.x4.shared.b16 {%0,%1,%2,%3}, [%4];" \
        : "=r"((d)[0]), "=r"((d)[1]), "=r"((d)[2]), "=r"((d)[3]) : "r"(addr))

#define MMAH(d, a, b0, b1) \
    asm volatile("mma.sync.aligned.m16n8k16.row.col.f32.f16.f16.f32 " \
        "{%0,%1,%2,%3}, {%4,%5,%6,%7}, {%8,%9}, {%0,%1,%2,%3};" \
        : "+f"((d)[0]), "+f"((d)[1]), "+f"((d)[2]), "+f"((d)[3]) \
        : "r"((a)[0]), "r"((a)[1]), "r"((a)[2]), "r"((a)[3]), "r"(b0), "r"(b1))

#define CP_ASYNC16(dst, src, sz) \
    asm volatile("cp.async.cg.shared.global [%0], [%1], 16, %2;" :: "r"(dst), "l"(src), "r"(sz))
#define CP_COMMIT()   asm volatile("cp.async.commit_group;")
#define CP_WAIT_ALL() asm volatile("cp.async.wait_group 0;")

// ===========================================================================
// init twiddle table (lane-only)
// ===========================================================================
__global__ void init_tw_kernel() {
    int lane = threadIdx.x;
    const double PI = 3.14159265358979323846;
    for (int j = 1; j <= 7; j++) {
        double th = -2.0 * PI * (double)(lane * j) / 256.0;
        twtab[lane][j-1] = make_float2((float)cos(th), (float)sin(th));
    }
    int d = 1;
    for (int s = 0; s < 5; s++) {
        double th = -PI * (double)(lane & (d-1)) / (double)d;
        twtab[lane][7+s] = make_float2((float)cos(th), (float)sin(th));
        d <<= 1;
    }
}

// ===========================================================================
// Prep: x NCHW fp32 -> xth [b][y][x][96] fp16 (smem transpose)
// ===========================================================================
__global__ __launch_bounds__(256) void prep_x_kernel(const float* __restrict__ x) {
    __shared__ float s[96][65];
    int blk = blockIdx.x;                 // 8*128*2
    int half = blk & 1, y = (blk >> 1) & 127, b = blk >> 8;
    int x0 = half * 64;
    for (int i = threadIdx.x; i < 96*64; i += 256) {
        int ci = i >> 6, xx = i & 63;
        s[ci][xx] = x[((b*96 + ci)*128 + y)*128 + x0 + xx];
    }
    __syncthreads();
    for (int i = threadIdx.x; i < 1536; i += 256) {   // 64 px * 24 uint2
        int px = i / 24, q = i % 24, ci0 = q * 4;
        size_t base = ((size_t)((b*128 + y)*128 + x0 + px)) * 96 + ci0;
        unsigned short h[4];
        #pragma unroll
        for (int k = 0; k < 4; k++) {
            __half hb = __float2half_rn(s[ci0 + k][px]);
            h[k] = __half_as_ushort(hb);
        }
        uint2 ho = make_uint2((uint32_t)h[0] | ((uint32_t)h[1] << 16), (uint32_t)h[2] | ((uint32_t)h[3] << 16));
        *(uint2*)(xth + base) = ho;
    }
}

// Prep weights: OIHW fp32 -> [tap][{wh,ew}][co][ci] fp16
__global__ __launch_bounds__(256) void prep_w_kernel(const float* __restrict__ w) {
    int i = blockIdx.x * 256 + threadIdx.x;     // 9*192*96
    if (i >= 9*192*96) return;
    int ci = i % 96, r = i / 96, co = r % 192, tap = r / 192;
    float v = w[(co*96 + ci)*9 + tap];
    __half hb = __float2half_rn(v);
    __half eb = __float2half_rn(v - __half2float(hb));
    wprep[((tap*2 + 0)*192 + co)*96 + ci] = hb;
    wprep[((tap*2 + 1)*192 + co)*96 + ci] = eb;
}

// ===========================================================================
// Conv 3x3 implicit-GEMM on mma.sync fp16 (2-product split xh*wh + xh*ew),
// cp.async pipelined. CTA: (batch,row) x n-chunk: M=128 px, N=64 co.
// 8 warps = 4(M) x 2(N), warp tile 32x32, 2 CTAs/SM.
// smem: A [130][208] at 0 (27040); B double buffer at 27040,
//       each buffer [2 kinds][64][208] (26624). Total 80288.
// ===========================================================================
#define AS_SZ   27040            // 130*208
#define B_OFF   27040
#define BS_SZ   13312            // 64*208
#define BBUF    26624            // 2*BS_SZ
#define CONV_SMEM 80288          // B_OFF + 2*BBUF

__global__ __launch_bounds__(256, 2) void conv_mma_kernel() {
    extern __shared__ char smem[];
    uint32_t sb = smem_to_u32(smem);
    int t = threadIdx.x, wid = t >> 5, l = t & 31;
    int blk = blockIdx.x;
    int b = blk >> 7, y = blk & 127;
    int ny = blockIdx.y;
    int wm = wid & 3, wn = wid >> 2;

    auto loadB = [&](int tap, int bb) {
        const char* base = (const char*)wprep + ((size_t)(tap*2*192 + ny*64)) * 192;
        #pragma unroll 4
        for (int i = t; i < 1536; i += 256) {           // 2 kinds * 64 rows * 12 x 16B
            int sp = i >= 768; int i2 = i - sp*768;
            int rr = i2 / 12, u = i2 % 12;
            uint32_t dst = sb + B_OFF + bb*BBUF + sp*BS_SZ + rr*208 + u*16;
            const char* src = base + ((size_t)(sp*192 + rr))*192 + u*16;
            CP_ASYNC16(dst, src, 16);
        }
    };
    auto loadA = [&](int ky) {
        int iy = y + ky - 1;
        bool rowok = (iy >= 0 && iy < 128);
        int iyc = iy < 0 ? 0 : (iy > 127 ? 127 : iy);
        #pragma unroll 4
        for (int i = t; i < 1560; i += 256) {           // 130 rows * 12 x 16B
            int rr = i / 12, u = i % 12;
            int ix = rr - 1;
            bool ok = rowok && ix >= 0 && ix < 128;
            int ixc = ix < 0 ? 0 : (ix > 127 ? 127 : ix);
            uint32_t dst = sb + rr*208 + u*16;
            const char* src = (const char*)xth + ((size_t)((b*128 + iyc)*128 + ixc))*192 + u*16;
            CP_ASYNC16(dst, src, ok ? 16 : 0);
        }
    };

    int j  = l >> 3, r8 = l & 7;
    int aRow = (j & 1) * 8 + r8;
    int aCol = (j >> 1) * 8;
    int bRow = (j & 1) * 8 + r8;
    int bCol = (j >> 1) * 8;

    float acc[2][4][4];
    #pragma unroll
    for (int mi = 0; mi < 2; mi++)
        #pragma unroll
        for (int nf = 0; nf < 4; nf++)
            #pragma unroll
            for (int e = 0; e < 4; e++) acc[mi][nf][e] = 0.f;

    loadA(0);
    loadB(0, 0);
    CP_COMMIT();
    CP_WAIT_ALL();
    __syncthreads();

    for (int tap = 0; tap < 9; tap++) {
        int kx = tap % 3, bb = tap & 1;
        if (tap < 8) { loadB(tap + 1, 1 - bb); CP_COMMIT(); }

        uint32_t aAddr = sb + (uint32_t)((wm*32 + kx + aRow) * 208 + aCol*2);
        uint32_t bH = sb + B_OFF + bb*BBUF + (uint32_t)((wn*32 + bRow) * 208 + bCol*2);
        uint32_t bL = bH + BS_SZ;

        #pragma unroll
        for (int ks = 0; ks < 6; ks++) {
            uint32_t bh[2][4], bl[2][4], a[2][4];
            #pragma unroll
            for (int np = 0; np < 2; np++) {
                LDMX4(bh[np], bH + np*(16*208) + ks*32);
                LDMX4(bl[np], bL + np*(16*208) + ks*32);
            }
            #pragma unroll
            for (int mi = 0; mi < 2; mi++)
                LDMX4(a[mi], aAddr + mi*(16*208) + ks*32);

            // product 1: xh * wh   (same-acc reuse distance = 8 MMAs)
            #pragma unroll
            for (int mi = 0; mi < 2; mi++)
                #pragma unroll
                for (int np = 0; np < 2; np++) {
                    MMAH(acc[mi][np*2+0], a[mi], bh[np][0], bh[np][2]);
                    MMAH(acc[mi][np*2+1], a[mi], bh[np][1], bh[np][3]);
                }
            // product 2: xh * ew
            #pragma unroll
            for (int mi = 0; mi < 2; mi++)
                #pragma unroll
                for (int np = 0; np < 2; np++) {
                    MMAH(acc[mi][np*2+0], a[mi], bl[np][0], bl[np][2]);
                    MMAH(acc[mi][np*2+1], a[mi], bl[np][1], bl[np][3]);
                }
        }

        if (tap < 8) {
            if (kx == 2) {
                __syncthreads();
                loadA(tap/3 + 1);
                CP_COMMIT();
            }
            CP_WAIT_ALL();
            __syncthreads();
        }
    }

    int gid = l >> 2, tid = l & 3;
    #pragma unroll
    for (int mi = 0; mi < 2; mi++) {
        #pragma unroll
        for (int nf = 0; nf < 4; nf++) {
            int co = ny*64 + wn*32 + nf*8 + 2*tid;
            int ch = co >> 2, ii = (co >> 1) & 1;
            size_t rowbase = ((size_t)(b*C2 + ch)*256 + (2*y + ii)) * 256;
            int ox0 = wm*32 + mi*16 + gid;
            *(float2*)(y_buf + rowbase + 2*ox0)       = make_float2(acc[mi][nf][0], acc[mi][nf][1]);
            *(float2*)(y_buf + rowbase + 2*(ox0 + 8)) = make_float2(acc[mi][nf][2], acc[mi][nf][3]);
        }
    }
}

// ===========================================================================
// complex helpers + SYMMETRIC-mask warp FFT lowpass
// ===========================================================================
__device__ __forceinline__ float2 cadd(float2 a, float2 b){ return make_float2(a.x+b.x, a.y+b.y); }
__device__ __forceinline__ float2 csub(float2 a, float2 b){ return make_float2(a.x-b.x, a.y-b.y); }
__device__ __forceinline__ float2 cmul(float2 a, float2 b){ return make_float2(a.x*b.x - a.y*b.y, a.x*b.y + a.y*b.x); }
__device__ __forceinline__ float2 cmulc(float2 a, float2 b){ return make_float2(a.x*b.x + a.y*b.y, a.y*b.x - a.x*b.y); }

template<int S>
__device__ __forceinline__ void fft8r(float2 v[8]) {
    const float s = (float)S;
    const float r = 0.70710678118654752f;
    float2 w1 = make_float2( r, s*r);
    float2 w3 = make_float2(-r, s*r);
    float2 t0=cadd(v[0],v[4]), t4=csub(v[0],v[4]);
    float2 t2=cadd(v[2],v[6]), t6=csub(v[2],v[6]);
    float2 t1=cadd(v[1],v[5]), t5=csub(v[1],v[5]);
    float2 t3=cadd(v[3],v[7]), t7=csub(v[3],v[7]);
    float2 rt6 = make_float2(-s*t6.y, s*t6.x);
    float2 rt7 = make_float2(-s*t7.y, s*t7.x);
    float2 u0=cadd(t0,t2), u2=csub(t0,t2);
    float2 u4=cadd(t4,rt6), u6=csub(t4,rt6);
    float2 u1=cadd(t1,t3), u3=csub(t1,t3);
    float2 u5=cadd(t5,rt7), u7=csub(t5,rt7);
    float2 ru3 = make_float2(-s*u3.y, s*u3.x);
    float2 wu5 = cmul(w1, u5);
    float2 wu7 = cmul(w3, u7);
    v[0]=cadd(u0,u1); v[4]=csub(u0,u1);
    v[2]=cadd(u2,ru3); v[6]=csub(u2,ru3);
    v[1]=cadd(u4,wu5); v[5]=csub(u4,wu5);
    v[3]=cadd(u6,wu7); v[7]=csub(u6,wu7);
}

__device__ __forceinline__ float2 shflxor2(float2 a, int d) {
    float2 r;
    r.x = __shfl_xor_sync(0xffffffffu, a.x, d);
    r.y = __shfl_xor_sync(0xffffffffu, a.y, d);
    return r;
}

__device__ __forceinline__ void lowpass_s(float2 v[8], int lane, const float2 tw[12]) {
    fft8r<-1>(v);
    #pragma unroll
    for (int j = 1; j < 8; j++) v[j] = cmul(v[j], tw[j-1]);
    #pragma unroll
    for (int s = 4; s >= 0; s--) {
        int d = 1 << s;
        float2 w = tw[7 + s];
        bool hi = (lane & d) != 0;
        #pragma unroll
        for (int j = 0; j < 8; j++) {
            float2 o = shflxor2(v[j], d);
            v[j] = hi ? cmul(csub(o, v[j]), w) : cadd(v[j], o);
        }
    }
    unsigned k1 = __brev((unsigned)lane) >> 27;
    if (k1 >= 8u && k1 < 24u) {
        #pragma unroll
        for (int j = 0; j < 8; j++) v[j] = make_float2(0.f, 0.f);
    } else if (k1 == 24u) {
        v[0] = make_float2(0.f, 0.f);
    }
    #pragma unroll
    for (int s = 0; s <= 4; s++) {
        int d = 1 << s;
        float2 w = tw[7 + s];
        bool hi = (lane & d) != 0;
        #pragma unroll
        for (int j = 0; j < 8; j++) {
            float2 a = v[j];
            if (hi) a = cmulc(a, w);
            float2 o = shflxor2(a, d);
            v[j] = hi ? csub(o, a) : cadd(a, o);
        }
    }
    #pragma unroll
    for (int j = 1; j < 8; j++) v[j] = cmulc(v[j], tw[j-1]);
    fft8r<1>(v);
    #pragma unroll
    for (int j = 0; j < 8; j++) { v[j].x *= 0.00390625f; v[j].y *= 0.00390625f; }
}

__device__ __forceinline__ float2 imul_pow(float s, int n) {
    switch (n & 3) {
        case 0:  return make_float2(s, 0.f);
        case 1:  return make_float2(0.f, s);
        case 2:  return make_float2(-s, 0.f);
        default: return make_float2(0.f, -s);
    }
}
__device__ __forceinline__ float2 rot_negi(float2 z, int n) {
    switch (n & 3) {
        case 0:  return z;
        case 1:  return make_float2(z.y, -z.x);
        case 2:  return make_float2(-z.x, -z.y);
        default: return make_float2(-z.y, z.x);
    }
}

// ===========================================================================
// p kernel: p[ch][m2] = sum_m1 y[ch][m1][m2] * i^m1   (CTA per channel)
// ===========================================================================
__global__ __launch_bounds__(256) void p_kernel() {
    int ch = blockIdx.x, m2 = threadIdx.x;
    const float* __restrict__ Y = y_buf + (size_t)ch * 65536;
    float pr = 0.f, pi = 0.f;
    #pragma unroll 4
    for (int m1 = 0; m1 < 256; m1 += 4) {
        pr += Y[(m1+0)*256 + m2];
        pi += Y[(m1+1)*256 + m2];
        pr -= Y[(m1+2)*256 + m2];
        pi -= Y[(m1+3)*256 + m2];
    }
    p_buf[ch*256 + m2] = make_float2(pr, pi);
}

// ===========================================================================
// Row lowpass (packed pairs) + q reduction.
// ===========================================================================
__global__ __launch_bounds__(256) void lp_rows_kernel() {
    int warp = threadIdx.x >> 5, lane = threadIdx.x & 31;
    float2 tw[12];
    #pragma unroll
    for (int i = 0; i < 12; i++) tw[i] = twtab[lane][i];

    int gu = blockIdx.x * 8 + warp;          // 0 .. NCH*128-1
    int ch = gu >> 7, r0 = (gu & 127) * 2;
    const float* __restrict__ srcA = y_buf + ((size_t)ch*256 + r0) * 256;
    const float* __restrict__ srcB = srcA + 256;

    float2 v[8];
    float sa = 0.f, sb = 0.f;
    #pragma unroll
    for (int j = 0; j < 8; j++) {
        float a = srcA[lane + 32*j], b = srcB[lane + 32*j];
        v[j] = make_float2(a, b);
        sa += a; sb += b;
    }
    float2 ca = imul_pow(sa, lane), cb = imul_pow(sb, lane);
    #pragma unroll
    for (int d = 16; d >= 1; d >>= 1) {
        ca.x += __shfl_xor_sync(0xffffffffu, ca.x, d);
        ca.y += __shfl_xor_sync(0xffffffffu, ca.y, d);
        cb.x += __shfl_xor_sync(0xffffffffu, cb.x, d);
        cb.y += __shfl_xor_sync(0xffffffffu, cb.y, d);
    }
    if (lane == 0) {
        q_buf[ch*256 + r0]     = ca;
        q_buf[ch*256 + r0 + 1] = cb;
    }

    lowpass_s(v, lane, tw);

    float* dstA = t_buf + ((size_t)ch*256 + r0) * 256;
    float* dstB = dstA + 256;
    #pragma unroll
    for (int j = 0; j < 8; j++) {
        dstA[lane + 32*j] = v[j].x;
        dstB[lane + 32*j] = v[j].y;
    }
}

// ===========================================================================
// hgc kernel
// ===========================================================================
__global__ __launch_bounds__(256) void hgc_kernel() {
    int warp = threadIdx.x >> 5, lane = threadIdx.x & 31;
    int ch = blockIdx.x * 8 + warp;
    float2 tw[12];
    #pragma unroll
    for (int i = 0; i < 12; i++) tw[i] = twtab[lane][i];

    float2 v[8];
    #pragma unroll
    for (int j = 0; j < 8; j++) v[j] = p_buf[ch*256 + lane + 32*j];

    float2 s = make_float2(0.f, 0.f);
    #pragma unroll
    for (int j = 0; j < 8; j++) s = cadd(s, v[j]);
    float2 w;
    switch (lane & 3) {
        case 0:  w = s; break;
        case 1:  w = make_float2(-s.y, s.x); break;
        case 2:  w = make_float2(-s.x, -s.y); break;
        default: w = make_float2(s.y, -s.x); break;
    }
    #pragma unroll
    for (int d = 16; d >= 1; d >>= 1) {
        w.x += __shfl_xor_sync(0xffffffffu, w.x, d);
        w.y += __shfl_xor_sync(0xffffffffu, w.y, d);
    }
    if (lane == 0) c_buf[ch] = make_float2(w.x * 1.52587890625e-5f, w.y * 1.52587890625e-5f);

    lowpass_s(v, lane, tw);
    #pragma unroll
    for (int j = 0; j < 8; j++)
        h_buf[ch*256 + lane + 32*j] = make_float2(v[j].x * 0.00390625f, v[j].y * 0.00390625f);

    #pragma unroll
    for (int j = 0; j < 8; j++) v[j] = q_buf[ch*256 + lane + 32*j];
    lowpass_s(v, lane, tw);
    #pragma unroll
    for (int j = 0; j < 8; j++)
        g_buf[ch*256 + lane + 32*j] = make_float2(v[j].x * 0.00390625f, v[j].y * 0.00390625f);
}

// ===========================================================================
// Column lowpass (packed col pairs) + rank-1 corrections + blend epilogue.
// ===========================================================================
__global__ __launch_bounds__(256) void lp_cols_kernel(
    const float* __restrict__ beta_ptr, float* __restrict__ out)
{
    __shared__ float st[256][17];
    int t  = threadIdx.x;
    int c0 = blockIdx.x * 16;
    int ch = blockIdx.y;
    size_t base = (size_t)ch * 65536;
    int warp = t >> 5, lane = t & 31;
    float2 tw[12];
    #pragma unroll
    for (int i = 0; i < 12; i++) tw[i] = twtab[lane][i];

    for (int idx = t; idx < 4096; idx += 256) {
        int row = idx >> 4, c = idx & 15;
        st[row][c] = t_buf[base + row*256 + c0 + c];
    }
    __syncthreads();

    {
        int n2A = c0 + 2*warp, n2B = n2A + 1;
        float2 v[8];
        #pragma unroll
        for (int j = 0; j < 8; j++)
            v[j] = make_float2(st[lane + 32*j][2*warp], st[lane + 32*j][2*warp + 1]);
        lowpass_s(v, lane, tw);

        float2 cc_ = c_buf[ch];
        float2 giA = rot_negi(make_float2(1.f, 0.f), n2A);
        float2 giB = rot_negi(make_float2(1.f, 0.f), n2B);
        float2 hcA = cadd(h_buf[ch*256 + n2A], cmul(cc_, giA));
        float2 hcB = cadd(h_buf[ch*256 + n2B], cmul(cc_, giB));

        #pragma unroll
        for (int j = 0; j < 8; j++) {
            int n1 = lane + 32*j;
            float2 g = g_buf[ch*256 + n1];
            float2 corrA = cadd(rot_negi(hcA, lane), cmul(g, giA));
            float2 corrB = cadd(rot_negi(hcB, lane), cmul(g, giB));
            float zAr = v[j].x + corrA.x, zAi = corrA.y;
            float zBr = v[j].y + corrB.x, zBi = corrB.y;
            st[n1][2*warp]     = sqrtf(zAr*zAr + zAi*zAi);
            st[n1][2*warp + 1] = sqrtf(zBr*zBr + zBi*zBi);
        }
    }
    __syncthreads();

    float beta = *beta_ptr;
    float cl   = 1.f - 2.f*beta;
    for (int idx = t; idx < 4096; idx += 256) {
        int row = idx >> 4, c = idx & 15;
        size_t o = base + row*256 + c0 + c;
        out[o] = beta * y_buf[o] + cl * st[row][c];
    }
}

// ---------------------------------------------------------------------------
extern "C" void kernel_launch(void* const* d_in, const int* in_sizes, int n_in,
                              void* d_out, int out_size)
{
    const float* x    = (const float*)d_in[0];
    const float* w    = (const float*)d_in[1];
    const float* beta = (const float*)d_in[2];
    float* out        = (float*)d_out;

    cudaFuncSetAttribute(conv_mma_kernel, cudaFuncAttributeMaxDynamicSharedMemorySize, CONV_SMEM);

    init_tw_kernel<<<1, 32>>>();
    prep_x_kernel<<<NB*128*2, 256>>>(x);
    prep_w_kernel<<<(9*192*96 + 255)/256, 256>>>(w);
    conv_mma_kernel<<<dim3(NB*128, 3), 256, CONV_SMEM>>>();
    p_kernel<<<NCH, 256>>>();
    lp_rows_kernel<<<NCH*128/8, 256>>>();
    hgc_kernel<<<NCH/8, 256>>>();
    lp_cols_kernel<<<dim3(16, NCH), 256>>>(beta, out);
}